// round 4
// baseline (speedup 1.0000x reference)
#include <cuda_runtime.h>

// Problem constants
#define Bc  8
#define Nn  20000
#define Ec  320000
#define Dd  128
#define MTOT (Bc * Nn)          // 160000 rows total
#define LEAKY 0.01f

// Scratch (static device globals — no allocation allowed)
__device__ float g_xw  [MTOT * Dd];   // x @ Wg
__device__ float g_conv[MTOT * Dd];   // aggregated conv output
__device__ float g_h1  [MTOT * Dd];   // hidden layer 1
__device__ float g_deg [MTOT];
__device__ float g_dinv[MTOT];

__device__ __forceinline__ float lrelu(float v) {
    return fmaxf(v, 0.0f) + LEAKY * fminf(v, 0.0f);
}

// ---------------------------------------------------------------------------
// Small kernels: degree / dinv
// ---------------------------------------------------------------------------
__global__ void k_zero_deg() {
    int i = blockIdx.x * blockDim.x + threadIdx.x;
    if (i < MTOT) g_deg[i] = 0.0f;
}

__global__ void k_degree(const int* __restrict__ ei) {
    int i = blockIdx.x * blockDim.x + threadIdx.x;
    if (i >= Bc * Ec) return;
    int b = i / Ec;
    int e = i - b * Ec;
    int dst = ei[(size_t)b * 2 * Ec + Ec + e];
    atomicAdd(&g_deg[b * Nn + dst], 1.0f);
}

__global__ void k_dinv() {
    int i = blockIdx.x * blockDim.x + threadIdx.x;
    if (i < MTOT) g_dinv[i] = rsqrtf(g_deg[i] + 1.0f);  // +1 self loop
}

// ---------------------------------------------------------------------------
// Edge scatter: conv[dst] += xw[src] * dinv[src]*dinv[dst]
// One warp per edge; each lane reduces a float4 via red.global.add.v4.f32
// ---------------------------------------------------------------------------
__global__ void k_scatter(const int* __restrict__ ei) {
    int gw   = (blockIdx.x * blockDim.x + threadIdx.x) >> 5;
    int lane = threadIdx.x & 31;
    if (gw >= Bc * Ec) return;
    int b = gw / Ec;
    int e = gw - b * Ec;
    const int* eb = ei + (size_t)b * 2 * Ec;
    int src = __ldg(&eb[e]);
    int dst = __ldg(&eb[Ec + e]);
    size_t rs = (size_t)b * Nn + src;
    size_t rd = (size_t)b * Nn + dst;
    float norm = g_dinv[rs] * g_dinv[rd];
    float4 v = *(const float4*)(g_xw + rs * Dd + lane * 4);
    v.x *= norm; v.y *= norm; v.z *= norm; v.w *= norm;
    float* p = g_conv + rd * Dd + lane * 4;
    asm volatile("red.global.add.v4.f32 [%0], {%1, %2, %3, %4};"
                 :: "l"(p), "f"(v.x), "f"(v.y), "f"(v.z), "f"(v.w)
                 : "memory");
}

// ---------------------------------------------------------------------------
// Fused SGEMM: [MTOT,128] @ [128,128], BM=BN=128, BK=16, 256 thr, 8x8/thread
// MODE 1: A = concat(nf,act);       out: g_xw, g_conv = xw*dinv^2 (self loop)
// MODE 2: A = relu(conv+bg)+x;      out: g_h1 = lrelu(A@W1 + b1)
// MODE 3: A = g_h1;                 out: out[row] = lrelu(A@W2+b2) @ W3 + b3
// ---------------------------------------------------------------------------
template <int MODE>
__global__ __launch_bounds__(256, 2)
void k_gemm(const float* __restrict__ nf, const float* __restrict__ act,
            const float* __restrict__ W,  const float* __restrict__ bias,
            const float* __restrict__ bg, const float* __restrict__ W3,
            const float* __restrict__ b3p, float* __restrict__ out)
{
    __shared__ float As[16][132];   // padded: 132*4B = 33*16B (f4-aligned rows)
    __shared__ float Bs[16][128];

    const int tid = threadIdx.x;
    const int tr  = tid >> 4;       // 0..15 : row group (8 rows)
    const int tc  = tid & 15;       // 0..15 : col group (8 cols)
    const size_t row0 = (size_t)blockIdx.x * 128;

    float acc[8][8];
#pragma unroll
    for (int i = 0; i < 8; i++)
#pragma unroll
        for (int j = 0; j < 8; j++) acc[i][j] = 0.0f;

    for (int kk = 0; kk < 128; kk += 16) {
        // ---- load W tile (coalesced float4) ----
#pragma unroll
        for (int v = 0; v < 2; v++) {
            int f = tid * 2 + v;            // 0..511
            int k = f >> 5;                 // 0..15
            int q = f & 31;                 // 0..31
            float4 w4 = *(const float4*)(W + (size_t)(kk + k) * 128 + q * 4);
            *(float4*)&Bs[k][q * 4] = w4;
        }
        // ---- load A tile (coalesced float4, transposed store) ----
#pragma unroll
        for (int v = 0; v < 2; v++) {
            int f = tid * 2 + v;            // 0..511
            int r = f >> 2;                 // 0..127
            int q = f & 3;                  // float4 index within BK
            size_t row = row0 + r;
            int kq = kk + q * 4;            // global k of first element
            float4 a4;
            if constexpr (MODE == 1) {
                const float* base = (kq < 64) ? (nf + row * 64 + kq)
                                              : (act + row * 64 + (kq - 64));
                a4 = *(const float4*)base;
            } else if constexpr (MODE == 2) {
                float4 c4 = *(const float4*)(g_conv + row * 128 + kq);
                float4 g4 = *(const float4*)(bg + kq);
                const float* base = (kq < 64) ? (nf + row * 64 + kq)
                                              : (act + row * 64 + (kq - 64));
                float4 x4 = *(const float4*)base;
                a4.x = fmaxf(c4.x + g4.x, 0.0f) + x4.x;
                a4.y = fmaxf(c4.y + g4.y, 0.0f) + x4.y;
                a4.z = fmaxf(c4.z + g4.z, 0.0f) + x4.z;
                a4.w = fmaxf(c4.w + g4.w, 0.0f) + x4.w;
            } else {
                a4 = *(const float4*)(g_h1 + row * 128 + kq);
            }
            As[q * 4 + 0][r] = a4.x;
            As[q * 4 + 1][r] = a4.y;
            As[q * 4 + 2][r] = a4.z;
            As[q * 4 + 3][r] = a4.w;
        }
        __syncthreads();

        // ---- mainloop ----
#pragma unroll
        for (int k = 0; k < 16; k++) {
            float a[8], b[8];
            float4 a0 = *(const float4*)&As[k][tr * 8];
            float4 a1 = *(const float4*)&As[k][tr * 8 + 4];
            a[0]=a0.x; a[1]=a0.y; a[2]=a0.z; a[3]=a0.w;
            a[4]=a1.x; a[5]=a1.y; a[6]=a1.z; a[7]=a1.w;
            float4 b0 = *(const float4*)&Bs[k][tc * 8];
            float4 b1 = *(const float4*)&Bs[k][tc * 8 + 4];
            b[0]=b0.x; b[1]=b0.y; b[2]=b0.z; b[3]=b0.w;
            b[4]=b1.x; b[5]=b1.y; b[6]=b1.z; b[7]=b1.w;
#pragma unroll
            for (int i = 0; i < 8; i++)
#pragma unroll
                for (int j = 0; j < 8; j++)
                    acc[i][j] = fmaf(a[i], b[j], acc[i][j]);
        }
        __syncthreads();
    }

    // ---- epilogue ----
    if constexpr (MODE == 1) {
#pragma unroll
        for (int i = 0; i < 8; i++) {
            size_t row = row0 + tr * 8 + i;
            float d = g_dinv[row];
            float s = d * d;
#pragma unroll
            for (int jq = 0; jq < 2; jq++) {
                float4 v;
                v.x = acc[i][jq * 4 + 0];
                v.y = acc[i][jq * 4 + 1];
                v.z = acc[i][jq * 4 + 2];
                v.w = acc[i][jq * 4 + 3];
                *(float4*)(g_xw + row * 128 + tc * 8 + jq * 4) = v;
                float4 c;
                c.x = v.x * s; c.y = v.y * s; c.z = v.z * s; c.w = v.w * s;
                *(float4*)(g_conv + row * 128 + tc * 8 + jq * 4) = c;
            }
        }
    } else if constexpr (MODE == 2) {
        float bj[8];
#pragma unroll
        for (int j = 0; j < 8; j++) bj[j] = bias[tc * 8 + j];
#pragma unroll
        for (int i = 0; i < 8; i++) {
            size_t row = row0 + tr * 8 + i;
#pragma unroll
            for (int jq = 0; jq < 2; jq++) {
                float4 v;
                v.x = lrelu(acc[i][jq * 4 + 0] + bj[jq * 4 + 0]);
                v.y = lrelu(acc[i][jq * 4 + 1] + bj[jq * 4 + 1]);
                v.z = lrelu(acc[i][jq * 4 + 2] + bj[jq * 4 + 2]);
                v.w = lrelu(acc[i][jq * 4 + 3] + bj[jq * 4 + 3]);
                *(float4*)(g_h1 + row * 128 + tc * 8 + jq * 4) = v;
            }
        }
    } else {
        float bj[8], w3r[8];
#pragma unroll
        for (int j = 0; j < 8; j++) {
            bj[j]  = bias[tc * 8 + j];
            w3r[j] = W3[tc * 8 + j];
        }
        float p[8];
#pragma unroll
        for (int i = 0; i < 8; i++) {
            float s = 0.0f;
#pragma unroll
            for (int j = 0; j < 8; j++) {
                float v = lrelu(acc[i][j] + bj[j]);
                s = fmaf(v, w3r[j], s);
            }
            p[i] = s;
        }
        __shared__ float red[128][17];
#pragma unroll
        for (int i = 0; i < 8; i++) red[tr * 8 + i][tc] = p[i];
        __syncthreads();
        if (tid < 128) {
            float s = 0.0f;
#pragma unroll
            for (int t = 0; t < 16; t++) s += red[tid][t];
            out[row0 + tid] = s + b3p[0];
        }
    }
}

// ---------------------------------------------------------------------------
extern "C" void kernel_launch(void* const* d_in, const int* in_sizes, int n_in,
                              void* d_out, int out_size)
{
    const float* nf  = (const float*)d_in[0];
    const float* act = (const float*)d_in[1];
    const int*   ei  = (const int*)d_in[2];     // JAX x64 disabled -> int32
    const float* Wg  = (const float*)d_in[3];
    const float* bg  = (const float*)d_in[4];
    const float* W1  = (const float*)d_in[5];
    const float* b1  = (const float*)d_in[6];
    const float* W2  = (const float*)d_in[7];
    const float* b2  = (const float*)d_in[8];
    const float* W3  = (const float*)d_in[9];
    const float* b3  = (const float*)d_in[10];
    float* out = (float*)d_out;

    k_zero_deg<<<(MTOT + 255) / 256, 256>>>();
    k_degree  <<<(Bc * Ec + 255) / 256, 256>>>(ei);
    k_dinv    <<<(MTOT + 255) / 256, 256>>>();

    // GEMM1: xw = concat(nf,act) @ Wg ; conv = xw * dinv^2  (self loop)
    k_gemm<1><<<MTOT / 128, 256>>>(nf, act, Wg, nullptr, nullptr, nullptr,
                                   nullptr, nullptr);
    // edge aggregation
    k_scatter<<<(Bc * Ec) / 8, 256>>>(ei);
    // GEMM2: h1 = lrelu((relu(conv+bg)+x) @ W1 + b1)
    k_gemm<2><<<MTOT / 128, 256>>>(nf, act, W1, b1, bg, nullptr, nullptr,
                                   nullptr);
    // GEMM3 (+ fused head): out = lrelu(h1 @ W2 + b2) @ W3 + b3
    k_gemm<3><<<MTOT / 128, 256>>>(nf, act, W2, b2, nullptr, W3, b3, out);
}

// round 5
// speedup vs baseline: 1.0201x; 1.0201x over previous
#include <cuda_runtime.h>

// Problem constants
#define Bc  8
#define Nn  20000
#define Ec  320000
#define Dd  128
#define MTOT (Bc * Nn)          // 160000 rows total
#define LEAKY 0.01f

// Scratch (static device globals — no allocation allowed)
__device__ float g_xw  [MTOT * Dd];   // x @ Wg
__device__ float g_conv[MTOT * Dd];   // aggregated conv output
__device__ float g_h1  [MTOT * Dd];   // hidden layer 1
__device__ float g_deg [MTOT];
__device__ float g_dinv[MTOT];

__device__ __forceinline__ float lrelu(float v) {
    return fmaxf(v, 0.0f) + LEAKY * fminf(v, 0.0f);
}

// ---- Blackwell packed f32x2 helpers (FFMA2: 2 MACs / instruction) ----
__device__ __forceinline__ unsigned long long dup2(float x) {
    unsigned long long r;
    asm("mov.b64 %0, {%1, %1};" : "=l"(r) : "f"(x));
    return r;
}
__device__ __forceinline__ void ffma2(unsigned long long& d,
                                      unsigned long long a,
                                      unsigned long long b) {
    asm("fma.rn.f32x2 %0, %1, %2, %0;" : "+l"(d) : "l"(a), "l"(b));
}
__device__ __forceinline__ void unpack2(unsigned long long v, float& x, float& y) {
    asm("mov.b64 {%0, %1}, %2;" : "=f"(x), "=f"(y) : "l"(v));
}
union F4U { float4 f; unsigned long long u[2]; };

// ---------------------------------------------------------------------------
// Small kernels: degree / dinv
// ---------------------------------------------------------------------------
__global__ void k_zero_deg() {
    int i = blockIdx.x * blockDim.x + threadIdx.x;
    if (i < MTOT) g_deg[i] = 0.0f;
}

__global__ void k_degree(const int* __restrict__ ei) {
    int i = blockIdx.x * blockDim.x + threadIdx.x;
    if (i >= Bc * Ec) return;
    int b = i / Ec;
    int e = i - b * Ec;
    int dst = ei[(size_t)b * 2 * Ec + Ec + e];
    atomicAdd(&g_deg[b * Nn + dst], 1.0f);
}

__global__ void k_dinv() {
    int i = blockIdx.x * blockDim.x + threadIdx.x;
    if (i < MTOT) g_dinv[i] = rsqrtf(g_deg[i] + 1.0f);  // +1 self loop
}

// ---------------------------------------------------------------------------
// Edge scatter: conv[dst] += xw[src] * dinv[src]*dinv[dst]
// One warp per edge; each lane reduces a float4 via red.global.add.v4.f32
// ---------------------------------------------------------------------------
__global__ void k_scatter(const int* __restrict__ ei) {
    int gw   = (blockIdx.x * blockDim.x + threadIdx.x) >> 5;
    int lane = threadIdx.x & 31;
    if (gw >= Bc * Ec) return;
    int b = gw / Ec;
    int e = gw - b * Ec;
    const int* eb = ei + (size_t)b * 2 * Ec;
    int src = __ldg(&eb[e]);
    int dst = __ldg(&eb[Ec + e]);
    size_t rs = (size_t)b * Nn + src;
    size_t rd = (size_t)b * Nn + dst;
    float norm = g_dinv[rs] * g_dinv[rd];
    float4 v = *(const float4*)(g_xw + rs * Dd + lane * 4);
    v.x *= norm; v.y *= norm; v.z *= norm; v.w *= norm;
    float* p = g_conv + rd * Dd + lane * 4;
    asm volatile("red.global.add.v4.f32 [%0], {%1, %2, %3, %4};"
                 :: "l"(p), "f"(v.x), "f"(v.y), "f"(v.z), "f"(v.w)
                 : "memory");
}

// ---------------------------------------------------------------------------
// Fused SGEMM: [MTOT,128] @ [128,128], BM=BN=128, BK=16, 256 thr, 8x8/thread
// Double-buffered smem pipeline + packed fma.rn.f32x2 mainloop.
// MODE 1: A = concat(nf,act);       out: g_xw, g_conv = xw*dinv^2 (self loop)
// MODE 2: A = relu(conv+bg)+x;      out: g_h1 = lrelu(A@W1 + b1)
// MODE 3: A = g_h1;                 out: out[row] = lrelu(A@W2+b2) @ W3 + b3
// ---------------------------------------------------------------------------
template <int MODE>
__global__ __launch_bounds__(256, 2)
void k_gemm(const float* __restrict__ nf, const float* __restrict__ act,
            const float* __restrict__ W,  const float* __restrict__ bias,
            const float* __restrict__ bg, const float* __restrict__ W3,
            const float* __restrict__ b3p, float* __restrict__ out)
{
    __shared__ float As[2][16][132];   // padded rows (16B-aligned, low conflict)
    __shared__ float Bs[2][16][128];

    const int tid = threadIdx.x;
    const int tr  = tid >> 4;       // 0..15 : row group (8 rows)
    const int tc  = tid & 15;       // 0..15 : col group (8 cols = 4 f32x2)
    const size_t row0 = (size_t)blockIdx.x * 128;
    const int f0 = tid * 2;

    unsigned long long acc2[8][4];  // acc2[i][j] packs cols (2j, 2j+1)
#pragma unroll
    for (int i = 0; i < 8; i++)
#pragma unroll
        for (int j = 0; j < 4; j++) acc2[i][j] = 0ull;

    float4 wreg[2], areg[2];        // register prefetch staging

    auto load_tile = [&](int kk) {
#pragma unroll
        for (int v = 0; v < 2; v++) {
            int f = f0 + v;
            int k = f >> 5, q = f & 31;
            wreg[v] = *(const float4*)(W + (size_t)(kk + k) * 128 + q * 4);
        }
#pragma unroll
        for (int v = 0; v < 2; v++) {
            int f = f0 + v;
            int r = f >> 2, q = f & 3;
            size_t row = row0 + r;
            int kq = kk + q * 4;
            float4 a4;
            if constexpr (MODE == 1) {
                const float* base = (kq < 64) ? (nf + row * 64 + kq)
                                              : (act + row * 64 + (kq - 64));
                a4 = *(const float4*)base;
            } else if constexpr (MODE == 2) {
                float4 c4 = *(const float4*)(g_conv + row * 128 + kq);
                float4 g4 = *(const float4*)(bg + kq);
                const float* base = (kq < 64) ? (nf + row * 64 + kq)
                                              : (act + row * 64 + (kq - 64));
                float4 x4 = *(const float4*)base;
                a4.x = fmaxf(c4.x + g4.x, 0.0f) + x4.x;
                a4.y = fmaxf(c4.y + g4.y, 0.0f) + x4.y;
                a4.z = fmaxf(c4.z + g4.z, 0.0f) + x4.z;
                a4.w = fmaxf(c4.w + g4.w, 0.0f) + x4.w;
            } else {
                a4 = *(const float4*)(g_h1 + row * 128 + kq);
            }
            areg[v] = a4;
        }
    };

    auto store_tile = [&](int buf) {
#pragma unroll
        for (int v = 0; v < 2; v++) {
            int f = f0 + v;
            int k = f >> 5, q = f & 31;
            *(float4*)&Bs[buf][k][q * 4] = wreg[v];
        }
#pragma unroll
        for (int v = 0; v < 2; v++) {
            int f = f0 + v;
            int r = f >> 2, q = f & 3;
            As[buf][q * 4 + 0][r] = areg[v].x;
            As[buf][q * 4 + 1][r] = areg[v].y;
            As[buf][q * 4 + 2][r] = areg[v].z;
            As[buf][q * 4 + 3][r] = areg[v].w;
        }
    };

    load_tile(0);
    store_tile(0);
    __syncthreads();

#pragma unroll 1
    for (int t = 0; t < 8; t++) {
        const int cur = t & 1;
        if (t < 7) load_tile((t + 1) * 16);      // global -> regs (overlapped)
#pragma unroll
        for (int k = 0; k < 16; k++) {
            float4 a0 = *(const float4*)&As[cur][k][tr * 8];
            float4 a1 = *(const float4*)&As[cur][k][tr * 8 + 4];
            F4U b0, b1;
            b0.f = *(const float4*)&Bs[cur][k][tc * 8];
            b1.f = *(const float4*)&Bs[cur][k][tc * 8 + 4];
            const unsigned long long bb0 = b0.u[0], bb1 = b0.u[1];
            const unsigned long long bb2 = b1.u[0], bb3 = b1.u[1];
            float av[8] = {a0.x, a0.y, a0.z, a0.w, a1.x, a1.y, a1.z, a1.w};
#pragma unroll
            for (int i = 0; i < 8; i++) {
                unsigned long long ad = dup2(av[i]);
                ffma2(acc2[i][0], ad, bb0);
                ffma2(acc2[i][1], ad, bb1);
                ffma2(acc2[i][2], ad, bb2);
                ffma2(acc2[i][3], ad, bb3);
            }
        }
        if (t < 7) {
            store_tile(1 - cur);                 // regs -> other smem buffer
            __syncthreads();                     // single sync per tile
        }
    }

    // ---- epilogue ----
    if constexpr (MODE == 1) {
#pragma unroll
        for (int i = 0; i < 8; i++) {
            size_t row = row0 + tr * 8 + i;
            float d = g_dinv[row];
            float s = d * d;
            float c[8];
#pragma unroll
            for (int j = 0; j < 4; j++) unpack2(acc2[i][j], c[2 * j], c[2 * j + 1]);
            float4 v0 = {c[0], c[1], c[2], c[3]};
            float4 v1 = {c[4], c[5], c[6], c[7]};
            *(float4*)(g_xw + row * 128 + tc * 8)     = v0;
            *(float4*)(g_xw + row * 128 + tc * 8 + 4) = v1;
            float4 q0 = {c[0] * s, c[1] * s, c[2] * s, c[3] * s};
            float4 q1 = {c[4] * s, c[5] * s, c[6] * s, c[7] * s};
            *(float4*)(g_conv + row * 128 + tc * 8)     = q0;
            *(float4*)(g_conv + row * 128 + tc * 8 + 4) = q1;
        }
    } else if constexpr (MODE == 2) {
        float bj[8];
#pragma unroll
        for (int j = 0; j < 8; j++) bj[j] = bias[tc * 8 + j];
#pragma unroll
        for (int i = 0; i < 8; i++) {
            size_t row = row0 + tr * 8 + i;
            float c[8];
#pragma unroll
            for (int j = 0; j < 4; j++) unpack2(acc2[i][j], c[2 * j], c[2 * j + 1]);
            float4 v0, v1;
            v0.x = lrelu(c[0] + bj[0]); v0.y = lrelu(c[1] + bj[1]);
            v0.z = lrelu(c[2] + bj[2]); v0.w = lrelu(c[3] + bj[3]);
            v1.x = lrelu(c[4] + bj[4]); v1.y = lrelu(c[5] + bj[5]);
            v1.z = lrelu(c[6] + bj[6]); v1.w = lrelu(c[7] + bj[7]);
            *(float4*)(g_h1 + row * 128 + tc * 8)     = v0;
            *(float4*)(g_h1 + row * 128 + tc * 8 + 4) = v1;
        }
    } else {
        float bj[8], w3r[8];
#pragma unroll
        for (int j = 0; j < 8; j++) {
            bj[j]  = bias[tc * 8 + j];
            w3r[j] = W3[tc * 8 + j];
        }
        float p[8];
#pragma unroll
        for (int i = 0; i < 8; i++) {
            float c[8];
#pragma unroll
            for (int j = 0; j < 4; j++) unpack2(acc2[i][j], c[2 * j], c[2 * j + 1]);
            float s = 0.0f;
#pragma unroll
            for (int j = 0; j < 8; j++) {
                float v = lrelu(c[j] + bj[j]);
                s = fmaf(v, w3r[j], s);
            }
            p[i] = s;
        }
        __shared__ float red[128][17];
#pragma unroll
        for (int i = 0; i < 8; i++) red[tr * 8 + i][tc] = p[i];
        __syncthreads();
        if (tid < 128) {
            float s = 0.0f;
#pragma unroll
            for (int t = 0; t < 16; t++) s += red[tid][t];
            out[row0 + tid] = s + b3p[0];
        }
    }
}

// ---------------------------------------------------------------------------
extern "C" void kernel_launch(void* const* d_in, const int* in_sizes, int n_in,
                              void* d_out, int out_size)
{
    const float* nf  = (const float*)d_in[0];
    const float* act = (const float*)d_in[1];
    const int*   ei  = (const int*)d_in[2];     // JAX x64 disabled -> int32
    const float* Wg  = (const float*)d_in[3];
    const float* bg  = (const float*)d_in[4];
    const float* W1  = (const float*)d_in[5];
    const float* b1  = (const float*)d_in[6];
    const float* W2  = (const float*)d_in[7];
    const float* b2  = (const float*)d_in[8];
    const float* W3  = (const float*)d_in[9];
    const float* b3  = (const float*)d_in[10];
    float* out = (float*)d_out;

    k_zero_deg<<<(MTOT + 255) / 256, 256>>>();
    k_degree  <<<(Bc * Ec + 255) / 256, 256>>>(ei);
    k_dinv    <<<(MTOT + 255) / 256, 256>>>();

    // GEMM1: xw = concat(nf,act) @ Wg ; conv = xw * dinv^2  (self loop)
    k_gemm<1><<<MTOT / 128, 256>>>(nf, act, Wg, nullptr, nullptr, nullptr,
                                   nullptr, nullptr);
    // edge aggregation
    k_scatter<<<(Bc * Ec) / 8, 256>>>(ei);
    // GEMM2: h1 = lrelu((relu(conv+bg)+x) @ W1 + b1)
    k_gemm<2><<<MTOT / 128, 256>>>(nf, act, W1, b1, bg, nullptr, nullptr,
                                   nullptr);
    // GEMM3 (+ fused head): out = lrelu(h1 @ W2 + b2) @ W3 + b3
    k_gemm<3><<<MTOT / 128, 256>>>(nf, act, W2, b2, nullptr, W3, b3, out);
}

// round 7
// speedup vs baseline: 1.2069x; 1.1831x over previous
#include <cuda_runtime.h>
#include <cuda_bf16.h>
#include <cstdint>

// Problem constants
#define Bc  8
#define Nn  20000
#define Ec  320000
#define MTOT (Bc * Nn)          // 160000 rows total
#define LEAKY 0.01f

// Padded bf16 tile: 128 rows x 136 cols (272 B pitch) = 34816 B
#define PITCH_B 272
#define BLOB_B  34816

// Scratch (static device globals — no allocation allowed)
__device__ float g_xw  [MTOT * 128];
__device__ float g_conv[MTOT * 128];
__device__ float g_h1  [MTOT * 128];
__device__ float g_deg [MTOT];
__device__ float g_dinv[MTOT];
// Pre-split W blobs in padded B-layout [n][k]: [matrix][hi/lo][BLOB_B/16]
__device__ uint4 g_wblob[3][2][BLOB_B / 16];

__device__ __forceinline__ float lrelu(float v) {
    return fmaxf(v, 0.0f) + LEAKY * fminf(v, 0.0f);
}
__device__ __forceinline__ uint32_t smem_u32(const void* p) {
    uint32_t a;
    asm("{ .reg .u64 t; cvta.to.shared.u64 t, %1; cvt.u32.u64 %0, t; }"
        : "=r"(a) : "l"(p));
    return a;
}
__device__ __forceinline__ void ldsm_x4(uint32_t addr, uint32_t r[4]) {
    asm volatile("ldmatrix.sync.aligned.m8n8.x4.shared.b16 {%0,%1,%2,%3}, [%4];"
                 : "=r"(r[0]), "=r"(r[1]), "=r"(r[2]), "=r"(r[3]) : "r"(addr));
}
__device__ __forceinline__ void mma16816(float* d, const uint32_t a[4],
                                         uint32_t b0, uint32_t b1) {
    asm volatile("mma.sync.aligned.m16n8k16.row.col.f32.bf16.bf16.f32 "
                 "{%0,%1,%2,%3}, {%4,%5,%6,%7}, {%8,%9}, {%0,%1,%2,%3};"
                 : "+f"(d[0]), "+f"(d[1]), "+f"(d[2]), "+f"(d[3])
                 : "r"(a[0]), "r"(a[1]), "r"(a[2]), "r"(a[3]), "r"(b0), "r"(b1));
}

// ---------------------------------------------------------------------------
// Small kernels
// ---------------------------------------------------------------------------
__global__ void k_zero_deg() {
    int i = blockIdx.x * blockDim.x + threadIdx.x;
    if (i < MTOT) g_deg[i] = 0.0f;
}
__global__ void k_degree(const int* __restrict__ ei) {
    int i = blockIdx.x * blockDim.x + threadIdx.x;
    if (i >= Bc * Ec) return;
    int b = i / Ec;
    int e = i - b * Ec;
    int dst = ei[(size_t)b * 2 * Ec + Ec + e];
    atomicAdd(&g_deg[b * Nn + dst], 1.0f);
}
__global__ void k_dinv() {
    int i = blockIdx.x * blockDim.x + threadIdx.x;
    if (i < MTOT) g_dinv[i] = rsqrtf(g_deg[i] + 1.0f);  // +1 self loop
}

// Split W ([in=K,out=N] row-major) into bf16 hi/lo blobs laid out [n][k], pitch 272B.
__global__ void k_prep_w(const float* __restrict__ Wg, const float* __restrict__ W1,
                         const float* __restrict__ W2) {
    int t = blockIdx.x * blockDim.x + threadIdx.x;   // 3 * 128 * 64
    if (t >= 3 * 8192) return;
    int m  = t >> 13;
    int r  = t & 8191;
    int n  = r >> 6;
    int cp = r & 63;                                  // k pair index
    const float* W = (m == 0) ? Wg : (m == 1) ? W1 : W2;
    float v0 = W[(2 * cp) * 128 + n];                 // B[n][2cp]   = W[2cp][n]
    float v1 = W[(2 * cp + 1) * 128 + n];
    __nv_bfloat162 hp, lp;
    hp.x = __float2bfloat16(v0);
    hp.y = __float2bfloat16(v1);
    lp.x = __float2bfloat16(v0 - __bfloat162float(hp.x));
    lp.y = __float2bfloat16(v1 - __bfloat162float(hp.y));
    int off = n * PITCH_B + cp * 4;
    *(uint32_t*)((char*)&g_wblob[m][0][0] + off) = *(uint32_t*)&hp;
    *(uint32_t*)((char*)&g_wblob[m][1][0] + off) = *(uint32_t*)&lp;
}

// ---------------------------------------------------------------------------
// Edge scatter: conv[dst] += xw[src] * dinv[src]*dinv[dst]
// ---------------------------------------------------------------------------
__global__ void k_scatter(const int* __restrict__ ei) {
    int gw   = (blockIdx.x * blockDim.x + threadIdx.x) >> 5;
    int lane = threadIdx.x & 31;
    if (gw >= Bc * Ec) return;
    int b = gw / Ec;
    int e = gw - b * Ec;
    const int* eb = ei + (size_t)b * 2 * Ec;
    int src = __ldg(&eb[e]);
    int dst = __ldg(&eb[Ec + e]);
    size_t rs = (size_t)b * Nn + src;
    size_t rd = (size_t)b * Nn + dst;
    float norm = g_dinv[rs] * g_dinv[rd];
    float4 v = *(const float4*)(g_xw + rs * 128 + lane * 4);
    v.x *= norm; v.y *= norm; v.z *= norm; v.w *= norm;
    float* p = g_conv + rd * 128 + lane * 4;
    asm volatile("red.global.add.v4.f32 [%0], {%1, %2, %3, %4};"
                 :: "l"(p), "f"(v.x), "f"(v.y), "f"(v.z), "f"(v.w)
                 : "memory");
}

// ---------------------------------------------------------------------------
// HMMA GEMM: CTA = 128 rows x 128 cols, 8 warps (4 row-groups x 2 col-groups),
// bf16x3 split (AhWh + AhWl + AlWh), fp32 accum via mma.sync.m16n8k16.
// MODE 1: A = concat(nf,act);   out: g_xw, g_conv = xw*dinv^2 (self loop)
// MODE 2: A = relu(conv+bg)+x;  out: g_h1 = lrelu(A@W1 + b1)
// MODE 3: A = g_h1;             out: out[row] = lrelu(A@W2+b2) @ W3 + b3
// ---------------------------------------------------------------------------
#define OFF_AH   0
#define OFF_AL   (BLOB_B)
#define OFF_WH   (2 * BLOB_B)
#define OFF_WL   (3 * BLOB_B)
#define OFF_BIAS (4 * BLOB_B)          // 512 B
#define OFF_W3   (4 * BLOB_B + 512)    // 512 B
#define OFF_RED  (4 * BLOB_B + 1024)   // 128*2*4 = 1024 B
#define SMEM_TOT (4 * BLOB_B + 2048)

template <int MODE>
__global__ __launch_bounds__(256)
void k_tc(const float* __restrict__ nf, const float* __restrict__ act,
          int widx, const float* __restrict__ bias,
          const float* __restrict__ bg, const float* __restrict__ W3,
          const float* __restrict__ b3p, float* __restrict__ out)
{
    extern __shared__ char smem[];
    const uint32_t sb = smem_u32(smem);
    const int tid  = threadIdx.x;
    const int wid  = tid >> 5;
    const int lane = tid & 31;
    const size_t row0 = (size_t)blockIdx.x * 128;

    // ---- copy W blobs (pre-split, pre-laid-out) ----
    {
        const uint4* wh = &g_wblob[widx][0][0];
        const uint4* wl = &g_wblob[widx][1][0];
        uint4* sh = (uint4*)(smem + OFF_WH);
        uint4* sl = (uint4*)(smem + OFF_WL);
        for (int i = tid; i < BLOB_B / 16; i += 256) { sh[i] = wh[i]; sl[i] = wl[i]; }
    }
    if (MODE >= 2 && tid < 32)
        ((float4*)(smem + OFF_BIAS))[tid] = ((const float4*)bias)[tid];
    if (MODE == 3 && tid >= 32 && tid < 64)
        ((float4*)(smem + OFF_W3))[tid - 32] = ((const float4*)W3)[tid - 32];

    // ---- build A: fp32 -> bf16 hi/lo, padded layout ----
    {
        int row  = tid >> 1;
        int half = tid & 1;
        size_t rowg = row0 + row;
        const float* srcx = half ? (act + rowg * 64) : (nf + rowg * 64);
        char* ah = smem + OFF_AH + row * PITCH_B + half * 128;
        char* al = smem + OFF_AL + row * PITCH_B + half * 128;
#pragma unroll
        for (int q = 0; q < 16; q++) {
            int c0 = half * 64 + q * 4;
            float4 a4;
            if constexpr (MODE == 1) {
                a4 = ((const float4*)srcx)[q];
            } else if constexpr (MODE == 2) {
                float4 c4 = *(const float4*)(g_conv + rowg * 128 + c0);
                float4 g4 = __ldg((const float4*)(bg + c0));
                float4 x4 = ((const float4*)srcx)[q];
                a4.x = fmaxf(c4.x + g4.x, 0.0f) + x4.x;
                a4.y = fmaxf(c4.y + g4.y, 0.0f) + x4.y;
                a4.z = fmaxf(c4.z + g4.z, 0.0f) + x4.z;
                a4.w = fmaxf(c4.w + g4.w, 0.0f) + x4.w;
            } else {
                a4 = *(const float4*)(g_h1 + rowg * 128 + c0);
            }
            __nv_bfloat162 hp, lp;
            hp.x = __float2bfloat16(a4.x); hp.y = __float2bfloat16(a4.y);
            lp.x = __float2bfloat16(a4.x - __bfloat162float(hp.x));
            lp.y = __float2bfloat16(a4.y - __bfloat162float(hp.y));
            *(uint32_t*)(ah + q * 8)     = *(uint32_t*)&hp;
            *(uint32_t*)(al + q * 8)     = *(uint32_t*)&lp;
            hp.x = __float2bfloat16(a4.z); hp.y = __float2bfloat16(a4.w);
            lp.x = __float2bfloat16(a4.z - __bfloat162float(hp.x));
            lp.y = __float2bfloat16(a4.w - __bfloat162float(hp.y));
            *(uint32_t*)(ah + q * 8 + 4) = *(uint32_t*)&hp;
            *(uint32_t*)(al + q * 8 + 4) = *(uint32_t*)&lp;
        }
    }
    __syncthreads();

    // ---- warp tiling: 32 rows x 64 cols per warp ----
    const int m0w = (wid >> 1) * 32;
    const int n0w = (wid & 1) * 64;

    float acc[2][8][4];
#pragma unroll
    for (int mt = 0; mt < 2; mt++)
#pragma unroll
        for (int nt = 0; nt < 8; nt++)
#pragma unroll
            for (int q = 0; q < 4; q++) acc[mt][nt][q] = 0.0f;

    // per-lane ldmatrix address offsets (within a blob)
    const uint32_t a_off = (uint32_t)(m0w + (lane & 15)) * PITCH_B
                         + ((lane >> 4) ? 16u : 0u);
    const uint32_t b_off = (uint32_t)(n0w + (lane & 7) + (lane >> 4) * 8) * PITCH_B
                         + (((lane >> 3) & 1) ? 16u : 0u);

    const uint32_t abase[3] = {sb + OFF_AH, sb + OFF_AH, sb + OFF_AL};
    const uint32_t bbase[3] = {sb + OFF_WH, sb + OFF_WL, sb + OFF_WH};

#pragma unroll 1
    for (int pass = 0; pass < 3; pass++) {
        uint32_t aaddr = abase[pass] + a_off;
        uint32_t baddr = bbase[pass] + b_off;
#pragma unroll
        for (int k = 0; k < 8; k++) {
            uint32_t af[2][4], bf[4][4];
            ldsm_x4(aaddr + k * 32,            af[0]);
            ldsm_x4(aaddr + k * 32 + 16 * PITCH_B, af[1]);
#pragma unroll
            for (int ng = 0; ng < 4; ng++)
                ldsm_x4(baddr + k * 32 + ng * 16 * PITCH_B, bf[ng]);
#pragma unroll
            for (int mt = 0; mt < 2; mt++)
#pragma unroll
                for (int nt = 0; nt < 8; nt++)
                    mma16816(acc[mt][nt], af[mt],
                             bf[nt >> 1][(nt & 1) * 2], bf[nt >> 1][(nt & 1) * 2 + 1]);
        }
    }

    // ---- epilogue ----
    const int gq = lane >> 2;          // row within 8-group
    const int tq = lane & 3;           // col pair selector
    if constexpr (MODE == 1) {
#pragma unroll
        for (int mt = 0; mt < 2; mt++) {
            size_t r0 = row0 + m0w + mt * 16 + gq;
            size_t r1 = r0 + 8;
            float d0 = g_dinv[r0], d1 = g_dinv[r1];
            float s0 = d0 * d0, s1 = d1 * d1;
#pragma unroll
            for (int nt = 0; nt < 8; nt++) {
                int c = n0w + nt * 8 + tq * 2;
                float* a = acc[mt][nt];
                *(float2*)(g_xw + r0 * 128 + c)   = make_float2(a[0], a[1]);
                *(float2*)(g_xw + r1 * 128 + c)   = make_float2(a[2], a[3]);
                *(float2*)(g_conv + r0 * 128 + c) = make_float2(a[0] * s0, a[1] * s0);
                *(float2*)(g_conv + r1 * 128 + c) = make_float2(a[2] * s1, a[3] * s1);
            }
        }
    } else if constexpr (MODE == 2) {
        const float* bias_s = (const float*)(smem + OFF_BIAS);
#pragma unroll
        for (int mt = 0; mt < 2; mt++) {
            size_t r0 = row0 + m0w + mt * 16 + gq;
            size_t r1 = r0 + 8;
#pragma unroll
            for (int nt = 0; nt < 8; nt++) {
                int c = n0w + nt * 8 + tq * 2;
                float b0 = bias_s[c], b1 = bias_s[c + 1];
                float* a = acc[mt][nt];
                *(float2*)(g_h1 + r0 * 128 + c) =
                    make_float2(lrelu(a[0] + b0), lrelu(a[1] + b1));
                *(float2*)(g_h1 + r1 * 128 + c) =
                    make_float2(lrelu(a[2] + b0), lrelu(a[3] + b1));
            }
        }
    } else {
        const float* bias_s = (const float*)(smem + OFF_BIAS);
        const float* w3_s   = (const float*)(smem + OFF_W3);
        float* red = (float*)(smem + OFF_RED);   // [128][2]
#pragma unroll
        for (int mt = 0; mt < 2; mt++) {
            float s0 = 0.0f, s1 = 0.0f;
#pragma unroll
            for (int nt = 0; nt < 8; nt++) {
                int c = n0w + nt * 8 + tq * 2;
                float b0 = bias_s[c], b1 = bias_s[c + 1];
                float w0 = w3_s[c],  w1 = w3_s[c + 1];
                float* a = acc[mt][nt];
                s0 = fmaf(lrelu(a[0] + b0), w0, s0);
                s0 = fmaf(lrelu(a[1] + b1), w1, s0);
                s1 = fmaf(lrelu(a[2] + b0), w0, s1);
                s1 = fmaf(lrelu(a[3] + b1), w1, s1);
            }
            // reduce over the 4 lanes sharing a row (tq = 0..3)
            s0 += __shfl_xor_sync(0xffffffffu, s0, 1);
            s0 += __shfl_xor_sync(0xffffffffu, s0, 2);
            s1 += __shfl_xor_sync(0xffffffffu, s1, 1);
            s1 += __shfl_xor_sync(0xffffffffu, s1, 2);
            if (tq == 0) {
                int lr0 = m0w + mt * 16 + gq;
                red[lr0 * 2 + (wid & 1)]       = s0;
                red[(lr0 + 8) * 2 + (wid & 1)] = s1;
            }
        }
        __syncthreads();
        if (tid < 128)
            out[row0 + tid] = red[tid * 2] + red[tid * 2 + 1] + __ldg(b3p);
    }
}

// ---------------------------------------------------------------------------
extern "C" void kernel_launch(void* const* d_in, const int* in_sizes, int n_in,
                              void* d_out, int out_size)
{
    const float* nf  = (const float*)d_in[0];
    const float* act = (const float*)d_in[1];
    const int*   ei  = (const int*)d_in[2];     // JAX x64 disabled -> int32
    const float* Wg  = (const float*)d_in[3];
    const float* bg  = (const float*)d_in[4];
    const float* W1  = (const float*)d_in[5];
    const float* b1  = (const float*)d_in[6];
    const float* W2  = (const float*)d_in[7];
    const float* b2  = (const float*)d_in[8];
    const float* W3  = (const float*)d_in[9];
    const float* b3  = (const float*)d_in[10];
    float* out = (float*)d_out;

    cudaFuncSetAttribute(k_tc<1>, cudaFuncAttributeMaxDynamicSharedMemorySize, SMEM_TOT);
    cudaFuncSetAttribute(k_tc<2>, cudaFuncAttributeMaxDynamicSharedMemorySize, SMEM_TOT);
    cudaFuncSetAttribute(k_tc<3>, cudaFuncAttributeMaxDynamicSharedMemorySize, SMEM_TOT);

    k_zero_deg<<<(MTOT + 255) / 256, 256>>>();
    k_degree  <<<(Bc * Ec + 255) / 256, 256>>>(ei);
    k_prep_w  <<<96, 256>>>(Wg, W1, W2);
    k_dinv    <<<(MTOT + 255) / 256, 256>>>();

    // GEMM1: xw = concat(nf,act) @ Wg ; conv = xw * dinv^2  (self loop)
    k_tc<1><<<MTOT / 128, 256, SMEM_TOT>>>(nf, act, 0, nullptr, nullptr,
                                           nullptr, nullptr, nullptr);
    // edge aggregation
    k_scatter<<<(Bc * Ec) / 8, 256>>>(ei);
    // GEMM2: h1 = lrelu((relu(conv+bg)+x) @ W1 + b1)
    k_tc<2><<<MTOT / 128, 256, SMEM_TOT>>>(nf, act, 1, b1, bg,
                                           nullptr, nullptr, nullptr);
    // GEMM3 (+ fused head): out = lrelu(h1 @ W2 + b2) @ W3 + b3
    k_tc<3><<<MTOT / 128, 256, SMEM_TOT>>>(nf, act, 2, b2, nullptr,
                                           W3, b3, out);
}

// round 8
// speedup vs baseline: 1.6737x; 1.3869x over previous
#include <cuda_runtime.h>
#include <cuda_bf16.h>
#include <cstdint>

// Problem constants
#define Bc  8
#define Nn  20000
#define Ec  320000
#define MTOT (Bc * Nn)          // 160000 rows total
#define NBLK 625                // MTOT / 256
#define LEAKY 0.01f

// Padded bf16 tile: 128 rows x 136 cols (272 B pitch) = 34816 B
#define PITCH_B 272
#define BLOB_B  34816

// Scratch (static device globals — no allocation allowed)
__device__ float g_xw  [MTOT * 128];
__device__ float g_conv[MTOT * 128];
__device__ float g_h1  [MTOT * 128];
__device__ float g_dinv[MTOT];
__device__ int   g_ideg[MTOT];
__device__ int   g_off [MTOT];
__device__ int   g_cur [MTOT];
__device__ int   g_bsum[NBLK];
__device__ int   g_sorted[Bc * Ec];
// Pre-split W blobs in padded B-layout [n][k]: [matrix][hi/lo][BLOB_B/16]
__device__ uint4 g_wblob[3][2][BLOB_B / 16];

__device__ __forceinline__ float lrelu(float v) {
    return fmaxf(v, 0.0f) + LEAKY * fminf(v, 0.0f);
}
__device__ __forceinline__ uint32_t smem_u32(const void* p) {
    uint32_t a;
    asm("{ .reg .u64 t; cvta.to.shared.u64 t, %1; cvt.u32.u64 %0, t; }"
        : "=r"(a) : "l"(p));
    return a;
}
__device__ __forceinline__ void ldsm_x4(uint32_t addr, uint32_t r[4]) {
    asm volatile("ldmatrix.sync.aligned.m8n8.x4.shared.b16 {%0,%1,%2,%3}, [%4];"
                 : "=r"(r[0]), "=r"(r[1]), "=r"(r[2]), "=r"(r[3]) : "r"(addr));
}
__device__ __forceinline__ void mma16816(float* d, const uint32_t a[4],
                                         uint32_t b0, uint32_t b1) {
    asm volatile("mma.sync.aligned.m16n8k16.row.col.f32.bf16.bf16.f32 "
                 "{%0,%1,%2,%3}, {%4,%5,%6,%7}, {%8,%9}, {%0,%1,%2,%3};"
                 : "+f"(d[0]), "+f"(d[1]), "+f"(d[2]), "+f"(d[3])
                 : "r"(a[0]), "r"(a[1]), "r"(a[2]), "r"(a[3]), "r"(b0), "r"(b1));
}

// ---------------------------------------------------------------------------
// Edge pipeline: degree -> scan -> reorder (counting sort by dst) -> aggregate
// ---------------------------------------------------------------------------
__global__ void k_zero_ideg() {
    int i = blockIdx.x * blockDim.x + threadIdx.x;
    if (i < MTOT) g_ideg[i] = 0;
}

__global__ void k_degree(const int* __restrict__ ei) {
    int i = blockIdx.x * blockDim.x + threadIdx.x;
    if (i >= Bc * Ec) return;
    int b = i / Ec;
    int e = i - b * Ec;
    int dst = ei[(size_t)b * 2 * Ec + Ec + e];
    atomicAdd(&g_ideg[b * Nn + dst], 1);
}

// Block-level scan: exclusive within block; per-block totals to g_bsum
__global__ void k_scanA() {
    __shared__ int s[256];
    int i = blockIdx.x * 256 + threadIdx.x;
    int v = g_ideg[i];
    s[threadIdx.x] = v;
    __syncthreads();
#pragma unroll
    for (int d = 1; d < 256; d <<= 1) {
        int t = (threadIdx.x >= d) ? s[threadIdx.x - d] : 0;
        __syncthreads();
        s[threadIdx.x] += t;
        __syncthreads();
    }
    g_off[i] = s[threadIdx.x] - v;
    if (threadIdx.x == 255) g_bsum[blockIdx.x] = s[255];
}

// Exclusive scan of the NBLK block sums (single block)
__global__ void k_scanB() {
    __shared__ int s[NBLK];
    int t = threadIdx.x;
    int v = (t < NBLK) ? g_bsum[t] : 0;
    if (t < NBLK) s[t] = v;
    __syncthreads();
    for (int d = 1; d < NBLK; d <<= 1) {
        int x = (t < NBLK && t >= d) ? s[t - d] : 0;
        __syncthreads();
        if (t < NBLK) s[t] += x;
        __syncthreads();
    }
    if (t < NBLK) g_bsum[t] = s[t] - v;
}

// Finalize offsets + cursor copy + dinv
__global__ void k_scanC() {
    int i = blockIdx.x * 256 + threadIdx.x;
    int o = g_off[i] + g_bsum[blockIdx.x];
    g_off[i] = o;
    g_cur[i] = o;
    g_dinv[i] = rsqrtf((float)g_ideg[i] + 1.0f);   // +1 self loop
}

__global__ void k_reorder(const int* __restrict__ ei) {
    int i = blockIdx.x * blockDim.x + threadIdx.x;
    if (i >= Bc * Ec) return;
    int b = i / Ec;
    int e = i - b * Ec;
    const int* eb = ei + (size_t)b * 2 * Ec;
    int src = __ldg(&eb[e]);
    int dst = __ldg(&eb[Ec + e]);
    int pos = atomicAdd(&g_cur[b * Nn + dst], 1);
    g_sorted[pos] = b * Nn + src;
}

// One warp per node: conv[i] = xw[i]*dinv[i]^2 + sum_e xw[src]*dinv[src]*dinv[i]
__global__ void k_aggregate() {
    int gw   = (blockIdx.x * blockDim.x + threadIdx.x) >> 5;
    int lane = threadIdx.x & 31;
    if (gw >= MTOT) return;
    const int off = g_off[gw];
    const int deg = g_ideg[gw];
    const float dv = g_dinv[gw];
    const int c = lane * 4;

    float4 acc = *(const float4*)(g_xw + (size_t)gw * 128 + c);
    float s = dv * dv;
    acc.x *= s; acc.y *= s; acc.z *= s; acc.w *= s;

    int e = 0;
    for (; e + 4 <= deg; e += 4) {
        int s0 = g_sorted[off + e + 0];
        int s1 = g_sorted[off + e + 1];
        int s2 = g_sorted[off + e + 2];
        int s3 = g_sorted[off + e + 3];
        float n0 = dv * g_dinv[s0];
        float n1 = dv * g_dinv[s1];
        float n2 = dv * g_dinv[s2];
        float n3 = dv * g_dinv[s3];
        float4 v0 = *(const float4*)(g_xw + (size_t)s0 * 128 + c);
        float4 v1 = *(const float4*)(g_xw + (size_t)s1 * 128 + c);
        float4 v2 = *(const float4*)(g_xw + (size_t)s2 * 128 + c);
        float4 v3 = *(const float4*)(g_xw + (size_t)s3 * 128 + c);
        acc.x += v0.x * n0 + v1.x * n1 + v2.x * n2 + v3.x * n3;
        acc.y += v0.y * n0 + v1.y * n1 + v2.y * n2 + v3.y * n3;
        acc.z += v0.z * n0 + v1.z * n1 + v2.z * n2 + v3.z * n3;
        acc.w += v0.w * n0 + v1.w * n1 + v2.w * n2 + v3.w * n3;
    }
    for (; e < deg; e++) {
        int s0 = g_sorted[off + e];
        float n0 = dv * g_dinv[s0];
        float4 v0 = *(const float4*)(g_xw + (size_t)s0 * 128 + c);
        acc.x += v0.x * n0; acc.y += v0.y * n0;
        acc.z += v0.z * n0; acc.w += v0.w * n0;
    }
    *(float4*)(g_conv + (size_t)gw * 128 + c) = acc;
}

// Split W ([in=K,out=N] row-major) into bf16 hi/lo blobs laid out [n][k], pitch 272B.
__global__ void k_prep_w(const float* __restrict__ Wg, const float* __restrict__ W1,
                         const float* __restrict__ W2) {
    int t = blockIdx.x * blockDim.x + threadIdx.x;   // 3 * 128 * 64
    if (t >= 3 * 8192) return;
    int m  = t >> 13;
    int r  = t & 8191;
    int n  = r >> 6;
    int cp = r & 63;                                  // k pair index
    const float* W = (m == 0) ? Wg : (m == 1) ? W1 : W2;
    float v0 = W[(2 * cp) * 128 + n];                 // B[n][2cp] = W[2cp][n]
    float v1 = W[(2 * cp + 1) * 128 + n];
    __nv_bfloat162 hp, lp;
    hp.x = __float2bfloat16(v0);
    hp.y = __float2bfloat16(v1);
    lp.x = __float2bfloat16(v0 - __bfloat162float(hp.x));
    lp.y = __float2bfloat16(v1 - __bfloat162float(hp.y));
    int off = n * PITCH_B + cp * 4;
    *(uint32_t*)((char*)&g_wblob[m][0][0] + off) = *(uint32_t*)&hp;
    *(uint32_t*)((char*)&g_wblob[m][1][0] + off) = *(uint32_t*)&lp;
}

// ---------------------------------------------------------------------------
// HMMA GEMM: CTA = 128 rows x 128 cols, 8 warps (4 row-groups x 2 col-groups),
// bf16x3 split (AhWh + AhWl + AlWh), fp32 accum via mma.sync.m16n8k16.
// MODE 1: A = concat(nf,act);   out: g_xw
// MODE 2: A = relu(conv+bg)+x;  out: g_h1 = lrelu(A@W1 + b1)
// MODE 3: A = g_h1;             out: out[row] = lrelu(A@W2+b2) @ W3 + b3
// ---------------------------------------------------------------------------
#define OFF_AH   0
#define OFF_AL   (BLOB_B)
#define OFF_WH   (2 * BLOB_B)
#define OFF_WL   (3 * BLOB_B)
#define OFF_BIAS (4 * BLOB_B)          // 512 B
#define OFF_W3   (4 * BLOB_B + 512)    // 512 B
#define OFF_RED  (4 * BLOB_B + 1024)   // 128*2*4 = 1024 B
#define SMEM_TOT (4 * BLOB_B + 2048)

template <int MODE>
__global__ __launch_bounds__(256)
void k_tc(const float* __restrict__ nf, const float* __restrict__ act,
          int widx, const float* __restrict__ bias,
          const float* __restrict__ bg, const float* __restrict__ W3,
          const float* __restrict__ b3p, float* __restrict__ out)
{
    extern __shared__ char smem[];
    const uint32_t sb = smem_u32(smem);
    const int tid  = threadIdx.x;
    const int wid  = tid >> 5;
    const int lane = tid & 31;
    const size_t row0 = (size_t)blockIdx.x * 128;

    // ---- copy W blobs (pre-split, pre-laid-out) ----
    {
        const uint4* wh = &g_wblob[widx][0][0];
        const uint4* wl = &g_wblob[widx][1][0];
        uint4* sh = (uint4*)(smem + OFF_WH);
        uint4* sl = (uint4*)(smem + OFF_WL);
        for (int i = tid; i < BLOB_B / 16; i += 256) { sh[i] = wh[i]; sl[i] = wl[i]; }
    }
    if (MODE >= 2 && tid < 32)
        ((float4*)(smem + OFF_BIAS))[tid] = ((const float4*)bias)[tid];
    if (MODE == 3 && tid >= 32 && tid < 64)
        ((float4*)(smem + OFF_W3))[tid - 32] = ((const float4*)W3)[tid - 32];

    // ---- build A: fp32 -> bf16 hi/lo, padded layout ----
    {
        int row  = tid >> 1;
        int half = tid & 1;
        size_t rowg = row0 + row;
        const float* srcx = half ? (act + rowg * 64) : (nf + rowg * 64);
        char* ah = smem + OFF_AH + row * PITCH_B + half * 128;
        char* al = smem + OFF_AL + row * PITCH_B + half * 128;
#pragma unroll
        for (int q = 0; q < 16; q++) {
            int c0 = half * 64 + q * 4;
            float4 a4;
            if constexpr (MODE == 1) {
                a4 = ((const float4*)srcx)[q];
            } else if constexpr (MODE == 2) {
                float4 c4 = *(const float4*)(g_conv + rowg * 128 + c0);
                float4 g4 = __ldg((const float4*)(bg + c0));
                float4 x4 = ((const float4*)srcx)[q];
                a4.x = fmaxf(c4.x + g4.x, 0.0f) + x4.x;
                a4.y = fmaxf(c4.y + g4.y, 0.0f) + x4.y;
                a4.z = fmaxf(c4.z + g4.z, 0.0f) + x4.z;
                a4.w = fmaxf(c4.w + g4.w, 0.0f) + x4.w;
            } else {
                a4 = *(const float4*)(g_h1 + rowg * 128 + c0);
            }
            __nv_bfloat162 hp, lp;
            hp.x = __float2bfloat16(a4.x); hp.y = __float2bfloat16(a4.y);
            lp.x = __float2bfloat16(a4.x - __bfloat162float(hp.x));
            lp.y = __float2bfloat16(a4.y - __bfloat162float(hp.y));
            *(uint32_t*)(ah + q * 8)     = *(uint32_t*)&hp;
            *(uint32_t*)(al + q * 8)     = *(uint32_t*)&lp;
            hp.x = __float2bfloat16(a4.z); hp.y = __float2bfloat16(a4.w);
            lp.x = __float2bfloat16(a4.z - __bfloat162float(hp.x));
            lp.y = __float2bfloat16(a4.w - __bfloat162float(hp.y));
            *(uint32_t*)(ah + q * 8 + 4) = *(uint32_t*)&hp;
            *(uint32_t*)(al + q * 8 + 4) = *(uint32_t*)&lp;
        }
    }
    __syncthreads();

    // ---- warp tiling: 32 rows x 64 cols per warp ----
    const int m0w = (wid >> 1) * 32;
    const int n0w = (wid & 1) * 64;

    float acc[2][8][4];
#pragma unroll
    for (int mt = 0; mt < 2; mt++)
#pragma unroll
        for (int nt = 0; nt < 8; nt++)
#pragma unroll
            for (int q = 0; q < 4; q++) acc[mt][nt][q] = 0.0f;

    const uint32_t a_off = (uint32_t)(m0w + (lane & 15)) * PITCH_B
                         + ((lane >> 4) ? 16u : 0u);
    const uint32_t b_off = (uint32_t)(n0w + (lane & 7) + (lane >> 4) * 8) * PITCH_B
                         + (((lane >> 3) & 1) ? 16u : 0u);

    const uint32_t abase[3] = {sb + OFF_AH, sb + OFF_AH, sb + OFF_AL};
    const uint32_t bbase[3] = {sb + OFF_WH, sb + OFF_WL, sb + OFF_WH};

#pragma unroll 1
    for (int pass = 0; pass < 3; pass++) {
        uint32_t aaddr = abase[pass] + a_off;
        uint32_t baddr = bbase[pass] + b_off;
#pragma unroll
        for (int k = 0; k < 8; k++) {
            uint32_t af[2][4], bf[4][4];
            ldsm_x4(aaddr + k * 32,                af[0]);
            ldsm_x4(aaddr + k * 32 + 16 * PITCH_B, af[1]);
#pragma unroll
            for (int ng = 0; ng < 4; ng++)
                ldsm_x4(baddr + k * 32 + ng * 16 * PITCH_B, bf[ng]);
#pragma unroll
            for (int mt = 0; mt < 2; mt++)
#pragma unroll
                for (int nt = 0; nt < 8; nt++)
                    mma16816(acc[mt][nt], af[mt],
                             bf[nt >> 1][(nt & 1) * 2], bf[nt >> 1][(nt & 1) * 2 + 1]);
        }
    }

    // ---- epilogue ----
    const int gq = lane >> 2;          // row within 8-group
    const int tq = lane & 3;           // col pair selector
    if constexpr (MODE == 1) {
#pragma unroll
        for (int mt = 0; mt < 2; mt++) {
            size_t r0 = row0 + m0w + mt * 16 + gq;
            size_t r1 = r0 + 8;
#pragma unroll
            for (int nt = 0; nt < 8; nt++) {
                int c = n0w + nt * 8 + tq * 2;
                float* a = acc[mt][nt];
                *(float2*)(g_xw + r0 * 128 + c) = make_float2(a[0], a[1]);
                *(float2*)(g_xw + r1 * 128 + c) = make_float2(a[2], a[3]);
            }
        }
    } else if constexpr (MODE == 2) {
        const float* bias_s = (const float*)(smem + OFF_BIAS);
#pragma unroll
        for (int mt = 0; mt < 2; mt++) {
            size_t r0 = row0 + m0w + mt * 16 + gq;
            size_t r1 = r0 + 8;
#pragma unroll
            for (int nt = 0; nt < 8; nt++) {
                int c = n0w + nt * 8 + tq * 2;
                float b0 = bias_s[c], b1 = bias_s[c + 1];
                float* a = acc[mt][nt];
                *(float2*)(g_h1 + r0 * 128 + c) =
                    make_float2(lrelu(a[0] + b0), lrelu(a[1] + b1));
                *(float2*)(g_h1 + r1 * 128 + c) =
                    make_float2(lrelu(a[2] + b0), lrelu(a[3] + b1));
            }
        }
    } else {
        const float* bias_s = (const float*)(smem + OFF_BIAS);
        const float* w3_s   = (const float*)(smem + OFF_W3);
        float* red = (float*)(smem + OFF_RED);   // [128][2]
#pragma unroll
        for (int mt = 0; mt < 2; mt++) {
            float s0 = 0.0f, s1 = 0.0f;
#pragma unroll
            for (int nt = 0; nt < 8; nt++) {
                int c = n0w + nt * 8 + tq * 2;
                float b0 = bias_s[c], b1 = bias_s[c + 1];
                float w0 = w3_s[c],  w1 = w3_s[c + 1];
                float* a = acc[mt][nt];
                s0 = fmaf(lrelu(a[0] + b0), w0, s0);
                s0 = fmaf(lrelu(a[1] + b1), w1, s0);
                s1 = fmaf(lrelu(a[2] + b0), w0, s1);
                s1 = fmaf(lrelu(a[3] + b1), w1, s1);
            }
            s0 += __shfl_xor_sync(0xffffffffu, s0, 1);
            s0 += __shfl_xor_sync(0xffffffffu, s0, 2);
            s1 += __shfl_xor_sync(0xffffffffu, s1, 1);
            s1 += __shfl_xor_sync(0xffffffffu, s1, 2);
            if (tq == 0) {
                int lr0 = m0w + mt * 16 + gq;
                red[lr0 * 2 + (wid & 1)]       = s0;
                red[(lr0 + 8) * 2 + (wid & 1)] = s1;
            }
        }
        __syncthreads();
        if (tid < 128)
            out[row0 + tid] = red[tid * 2] + red[tid * 2 + 1] + __ldg(b3p);
    }
}

// ---------------------------------------------------------------------------
extern "C" void kernel_launch(void* const* d_in, const int* in_sizes, int n_in,
                              void* d_out, int out_size)
{
    const float* nf  = (const float*)d_in[0];
    const float* act = (const float*)d_in[1];
    const int*   ei  = (const int*)d_in[2];     // JAX x64 disabled -> int32
    const float* Wg  = (const float*)d_in[3];
    const float* bg  = (const float*)d_in[4];
    const float* W1  = (const float*)d_in[5];
    const float* b1  = (const float*)d_in[6];
    const float* W2  = (const float*)d_in[7];
    const float* b2  = (const float*)d_in[8];
    const float* W3  = (const float*)d_in[9];
    const float* b3  = (const float*)d_in[10];
    float* out = (float*)d_out;

    cudaFuncSetAttribute(k_tc<1>, cudaFuncAttributeMaxDynamicSharedMemorySize, SMEM_TOT);
    cudaFuncSetAttribute(k_tc<2>, cudaFuncAttributeMaxDynamicSharedMemorySize, SMEM_TOT);
    cudaFuncSetAttribute(k_tc<3>, cudaFuncAttributeMaxDynamicSharedMemorySize, SMEM_TOT);

    // Edge indexing structure (counting sort by dst)
    k_zero_ideg<<<NBLK, 256>>>();
    k_degree   <<<(Bc * Ec + 255) / 256, 256>>>(ei);
    k_scanA    <<<NBLK, 256>>>();
    k_scanB    <<<1, 1024>>>();
    k_scanC    <<<NBLK, 256>>>();
    k_reorder  <<<(Bc * Ec + 255) / 256, 256>>>(ei);
    k_prep_w   <<<96, 256>>>(Wg, W1, W2);

    // GEMM1: xw = concat(nf,act) @ Wg
    k_tc<1><<<MTOT / 128, 256, SMEM_TOT>>>(nf, act, 0, nullptr, nullptr,
                                           nullptr, nullptr, nullptr);
    // conv = self-loop + gather-aggregate (no atomics)
    k_aggregate<<<(MTOT * 32 + 255) / 256, 256>>>();
    // GEMM2: h1 = lrelu((relu(conv+bg)+x) @ W1 + b1)
    k_tc<2><<<MTOT / 128, 256, SMEM_TOT>>>(nf, act, 1, b1, bg,
                                           nullptr, nullptr, nullptr);
    // GEMM3 (+ fused head): out = lrelu(h1 @ W2 + b2) @ W3 + b3
    k_tc<3><<<MTOT / 128, 256, SMEM_TOT>>>(nf, act, 2, b2, nullptr,
                                           W3, b3, out);
}

// round 11
// speedup vs baseline: 1.7169x; 1.0258x over previous
#include <cuda_runtime.h>
#include <cuda_bf16.h>
#include <cuda_fp16.h>
#include <cstdint>

// Problem constants
#define Bc  8
#define Nn  20000
#define Ec  320000
#define MTOT (Bc * Nn)          // 160000 rows total
#define NBLK 625                // MTOT / 256
#define LEAKY 0.01f

// Padded bf16 tile: 128 rows x 136 cols (272 B pitch) = 34816 B
#define PITCH_B 272
#define BLOB_B  34816

// Scratch (static device globals — no allocation allowed)
__device__ __half g_xwh[MTOT * 128];   // x @ Wg, fp16 payload for aggregation
__device__ float  g_conv[MTOT * 128];
__device__ float  g_h1  [MTOT * 128];
__device__ float  g_dinv[MTOT];
__device__ int    g_ideg[MTOT];
__device__ int    g_off [MTOT];
__device__ int    g_cur [MTOT];
__device__ int    g_bsum[NBLK];
__device__ int    g_sorted[Bc * Ec];
// Pre-split W blobs in padded B-layout [n][k]: [matrix][hi/lo][BLOB_B/16]
__device__ uint4  g_wblob[3][2][BLOB_B / 16];

__device__ __forceinline__ float lrelu(float v) {
    return fmaxf(v, 0.0f) + LEAKY * fminf(v, 0.0f);
}
__device__ __forceinline__ uint32_t smem_u32(const void* p) {
    uint32_t a;
    asm("{ .reg .u64 t; cvta.to.shared.u64 t, %1; cvt.u32.u64 %0, t; }"
        : "=r"(a) : "l"(p));
    return a;
}
__device__ __forceinline__ void ldsm_x4(uint32_t addr, uint32_t r[4]) {
    asm volatile("ldmatrix.sync.aligned.m8n8.x4.shared.b16 {%0,%1,%2,%3}, [%4];"
                 : "=r"(r[0]), "=r"(r[1]), "=r"(r[2]), "=r"(r[3]) : "r"(addr));
}
__device__ __forceinline__ void mma16816(float* d, const uint32_t a[4],
                                         uint32_t b0, uint32_t b1) {
    asm volatile("mma.sync.aligned.m16n8k16.row.col.f32.bf16.bf16.f32 "
                 "{%0,%1,%2,%3}, {%4,%5,%6,%7}, {%8,%9}, {%0,%1,%2,%3};"
                 : "+f"(d[0]), "+f"(d[1]), "+f"(d[2]), "+f"(d[3])
                 : "r"(a[0]), "r"(a[1]), "r"(a[2]), "r"(a[3]), "r"(b0), "r"(b1));
}

// ---------------------------------------------------------------------------
// Edge pipeline: degree -> scan -> reorder (counting sort by dst) -> aggregate
// ---------------------------------------------------------------------------
__global__ void k_zero_ideg() {
    int i = blockIdx.x * blockDim.x + threadIdx.x;
    if (i < MTOT) g_ideg[i] = 0;
}

__global__ void k_degree(const int* __restrict__ ei) {
    int i = blockIdx.x * blockDim.x + threadIdx.x;
    if (i >= Bc * Ec) return;
    int b = i / Ec;
    int e = i - b * Ec;
    int dst = ei[(size_t)b * 2 * Ec + Ec + e];
    atomicAdd(&g_ideg[b * Nn + dst], 1);
}

// Block-level scan: exclusive within block; per-block totals to g_bsum
__global__ void k_scanA() {
    __shared__ int s[256];
    int i = blockIdx.x * 256 + threadIdx.x;
    int v = g_ideg[i];
    s[threadIdx.x] = v;
    __syncthreads();
#pragma unroll
    for (int d = 1; d < 256; d <<= 1) {
        int t = (threadIdx.x >= d) ? s[threadIdx.x - d] : 0;
        __syncthreads();
        s[threadIdx.x] += t;
        __syncthreads();
    }
    g_off[i] = s[threadIdx.x] - v;
    if (threadIdx.x == 255) g_bsum[blockIdx.x] = s[255];
}

// Exclusive scan of the NBLK block sums (single block)
__global__ void k_scanB() {
    __shared__ int s[NBLK];
    int t = threadIdx.x;
    int v = (t < NBLK) ? g_bsum[t] : 0;
    if (t < NBLK) s[t] = v;
    __syncthreads();
    for (int d = 1; d < NBLK; d <<= 1) {
        int x = (t < NBLK && t >= d) ? s[t - d] : 0;
        __syncthreads();
        if (t < NBLK) s[t] += x;
        __syncthreads();
    }
    if (t < NBLK) g_bsum[t] = s[t] - v;
}

// Finalize offsets + cursor copy + dinv
__global__ void k_scanC() {
    int i = blockIdx.x * 256 + threadIdx.x;
    int o = g_off[i] + g_bsum[blockIdx.x];
    g_off[i] = o;
    g_cur[i] = o;
    g_dinv[i] = rsqrtf((float)g_ideg[i] + 1.0f);   // +1 self loop
}

__global__ void k_reorder(const int* __restrict__ ei) {
    int i = blockIdx.x * blockDim.x + threadIdx.x;
    if (i >= Bc * Ec) return;
    int b = i / Ec;
    int e = i - b * Ec;
    const int* eb = ei + (size_t)b * 2 * Ec;
    int src = __ldg(&eb[e]);
    int dst = __ldg(&eb[Ec + e]);
    int pos = atomicAdd(&g_cur[b * Nn + dst], 1);
    g_sorted[pos] = b * Nn + src;
}

// One warp per node: conv[i] = xw[i]*dinv[i]^2 + sum_e xw[src]*dinv[src]*dinv[i]
// fp16 gather payload (halves L2 traffic), fp32 accumulation.
__global__ void k_aggregate() {
    int gw   = (blockIdx.x * blockDim.x + threadIdx.x) >> 5;
    int lane = threadIdx.x & 31;
    if (gw >= MTOT) return;
    const int off = g_off[gw];
    const int deg = g_ideg[gw];
    const float dv = g_dinv[gw];
    const int c = lane * 4;

    const __half2* self = (const __half2*)(g_xwh + (size_t)gw * 128 + c);
    float2 sx = __half22float2(self[0]);
    float2 sy = __half22float2(self[1]);
    float s = dv * dv;
    float ax = sx.x * s, ay = sx.y * s, az = sy.x * s, aw = sy.y * s;

    int e = 0;
    for (; e + 4 <= deg; e += 4) {
        int s0 = g_sorted[off + e + 0];
        int s1 = g_sorted[off + e + 1];
        int s2 = g_sorted[off + e + 2];
        int s3 = g_sorted[off + e + 3];
        float n0 = dv * g_dinv[s0];
        float n1 = dv * g_dinv[s1];
        float n2 = dv * g_dinv[s2];
        float n3 = dv * g_dinv[s3];
        const __half2* p0 = (const __half2*)(g_xwh + (size_t)s0 * 128 + c);
        const __half2* p1 = (const __half2*)(g_xwh + (size_t)s1 * 128 + c);
        const __half2* p2 = (const __half2*)(g_xwh + (size_t)s2 * 128 + c);
        const __half2* p3 = (const __half2*)(g_xwh + (size_t)s3 * 128 + c);
        float2 u0 = __half22float2(p0[0]), w0 = __half22float2(p0[1]);
        float2 u1 = __half22float2(p1[0]), w1 = __half22float2(p1[1]);
        float2 u2 = __half22float2(p2[0]), w2 = __half22float2(p2[1]);
        float2 u3 = __half22float2(p3[0]), w3 = __half22float2(p3[1]);
        ax += u0.x * n0 + u1.x * n1 + u2.x * n2 + u3.x * n3;
        ay += u0.y * n0 + u1.y * n1 + u2.y * n2 + u3.y * n3;
        az += w0.x * n0 + w1.x * n1 + w2.x * n2 + w3.x * n3;
        aw += w0.y * n0 + w1.y * n1 + w2.y * n2 + w3.y * n3;
    }
    for (; e < deg; e++) {
        int s0 = g_sorted[off + e];
        float n0 = dv * g_dinv[s0];
        const __half2* p0 = (const __half2*)(g_xwh + (size_t)s0 * 128 + c);
        float2 u0 = __half22float2(p0[0]), w0 = __half22float2(p0[1]);
        ax += u0.x * n0; ay += u0.y * n0;
        az += w0.x * n0; aw += w0.y * n0;
    }
    *(float4*)(g_conv + (size_t)gw * 128 + c) = make_float4(ax, ay, az, aw);
}

// Split W ([in=K,out=N] row-major) into bf16 hi/lo blobs laid out [n][k], pitch 272B.
__global__ void k_prep_w(const float* __restrict__ Wg, const float* __restrict__ W1,
                         const float* __restrict__ W2) {
    int t = blockIdx.x * blockDim.x + threadIdx.x;   // 3 * 128 * 64
    if (t >= 3 * 8192) return;
    int m  = t >> 13;
    int r  = t & 8191;
    int n  = r >> 6;
    int cp = r & 63;                                  // k pair index
    const float* W = (m == 0) ? Wg : (m == 1) ? W1 : W2;
    float v0 = W[(2 * cp) * 128 + n];                 // B[n][2cp] = W[2cp][n]
    float v1 = W[(2 * cp + 1) * 128 + n];
    __nv_bfloat162 hp, lp;
    hp.x = __float2bfloat16(v0);
    hp.y = __float2bfloat16(v1);
    lp.x = __float2bfloat16(v0 - __bfloat162float(hp.x));
    lp.y = __float2bfloat16(v1 - __bfloat162float(hp.y));
    int off = n * PITCH_B + cp * 4;
    *(uint32_t*)((char*)&g_wblob[m][0][0] + off) = *(uint32_t*)&hp;
    *(uint32_t*)((char*)&g_wblob[m][1][0] + off) = *(uint32_t*)&lp;
}

// ---------------------------------------------------------------------------
// HMMA GEMM: CTA = 128 rows x 128 cols, 8 warps (4 row-groups x 2 col-groups),
// bf16x3 split (AhWh + AhWl + AlWh), fp32 accum via mma.sync.m16n8k16.
// MODE 1: A = concat(nf,act);   out: g_xwh (fp16)
// MODE 2: A = relu(conv+bg)+x;  out: g_h1 = lrelu(A@W1 + b1)
// MODE 3: A = g_h1;             out: out[row] = lrelu(A@W2+b2) @ W3 + b3
// ---------------------------------------------------------------------------
#define OFF_AH   0
#define OFF_AL   (BLOB_B)
#define OFF_WH   (2 * BLOB_B)
#define OFF_WL   (3 * BLOB_B)
#define OFF_BIAS (4 * BLOB_B)          // 512 B
#define OFF_W3   (4 * BLOB_B + 512)    // 512 B
#define OFF_RED  (4 * BLOB_B + 1024)   // 128*2*4 = 1024 B
#define SMEM_TOT (4 * BLOB_B + 2048)

template <int MODE>
__global__ __launch_bounds__(256)
void k_tc(const float* __restrict__ nf, const float* __restrict__ act,
          int widx, const float* __restrict__ bias,
          const float* __restrict__ bg, const float* __restrict__ W3,
          const float* __restrict__ b3p, float* __restrict__ out)
{
    extern __shared__ char smem[];
    const uint32_t sb = smem_u32(smem);
    const int tid  = threadIdx.x;
    const int wid  = tid >> 5;
    const int lane = tid & 31;
    const size_t row0 = (size_t)blockIdx.x * 128;

    // ---- copy W blobs (pre-split, pre-laid-out) ----
    {
        const uint4* wh = &g_wblob[widx][0][0];
        const uint4* wl = &g_wblob[widx][1][0];
        uint4* sh = (uint4*)(smem + OFF_WH);
        uint4* sl = (uint4*)(smem + OFF_WL);
        for (int i = tid; i < BLOB_B / 16; i += 256) { sh[i] = wh[i]; sl[i] = wl[i]; }
    }
    if (MODE >= 2 && tid < 32)
        ((float4*)(smem + OFF_BIAS))[tid] = ((const float4*)bias)[tid];
    if (MODE == 3 && tid >= 32 && tid < 64)
        ((float4*)(smem + OFF_W3))[tid - 32] = ((const float4*)W3)[tid - 32];

    // ---- build A: fp32 -> bf16 hi/lo, padded layout ----
    {
        int row  = tid >> 1;
        int half = tid & 1;
        size_t rowg = row0 + row;
        const float* srcx = half ? (act + rowg * 64) : (nf + rowg * 64);
        char* ah = smem + OFF_AH + row * PITCH_B + half * 128;
        char* al = smem + OFF_AL + row * PITCH_B + half * 128;
#pragma unroll
        for (int q = 0; q < 16; q++) {
            int c0 = half * 64 + q * 4;
            float4 a4;
            if constexpr (MODE == 1) {
                a4 = ((const float4*)srcx)[q];
            } else if constexpr (MODE == 2) {
                float4 c4 = *(const float4*)(g_conv + rowg * 128 + c0);
                float4 g4 = __ldg((const float4*)(bg + c0));
                float4 x4 = ((const float4*)srcx)[q];
                a4.x = fmaxf(c4.x + g4.x, 0.0f) + x4.x;
                a4.y = fmaxf(c4.y + g4.y, 0.0f) + x4.y;
                a4.z = fmaxf(c4.z + g4.z, 0.0f) + x4.z;
                a4.w = fmaxf(c4.w + g4.w, 0.0f) + x4.w;
            } else {
                a4 = *(const float4*)(g_h1 + rowg * 128 + c0);
            }
            __nv_bfloat162 hp, lp;
            hp.x = __float2bfloat16(a4.x); hp.y = __float2bfloat16(a4.y);
            lp.x = __float2bfloat16(a4.x - __bfloat162float(hp.x));
            lp.y = __float2bfloat16(a4.y - __bfloat162float(hp.y));
            *(uint32_t*)(ah + q * 8)     = *(uint32_t*)&hp;
            *(uint32_t*)(al + q * 8)     = *(uint32_t*)&lp;
            hp.x = __float2bfloat16(a4.z); hp.y = __float2bfloat16(a4.w);
            lp.x = __float2bfloat16(a4.z - __bfloat162float(hp.x));
            lp.y = __float2bfloat16(a4.w - __bfloat162float(hp.y));
            *(uint32_t*)(ah + q * 8 + 4) = *(uint32_t*)&hp;
            *(uint32_t*)(al + q * 8 + 4) = *(uint32_t*)&lp;
        }
    }
    __syncthreads();

    // ---- warp tiling: 32 rows x 64 cols per warp ----
    const int m0w = (wid >> 1) * 32;
    const int n0w = (wid & 1) * 64;

    float acc[2][8][4];
#pragma unroll
    for (int mt = 0; mt < 2; mt++)
#pragma unroll
        for (int nt = 0; nt < 8; nt++)
#pragma unroll
            for (int q = 0; q < 4; q++) acc[mt][nt][q] = 0.0f;

    const uint32_t a_off = (uint32_t)(m0w + (lane & 15)) * PITCH_B
                         + ((lane >> 4) ? 16u : 0u);
    const uint32_t b_off = (uint32_t)(n0w + (lane & 7) + (lane >> 4) * 8) * PITCH_B
                         + (((lane >> 3) & 1) ? 16u : 0u);

    const uint32_t abase[3] = {sb + OFF_AH, sb + OFF_AH, sb + OFF_AL};
    const uint32_t bbase[3] = {sb + OFF_WH, sb + OFF_WL, sb + OFF_WH};

#pragma unroll 1
    for (int pass = 0; pass < 3; pass++) {
        uint32_t aaddr = abase[pass] + a_off;
        uint32_t baddr = bbase[pass] + b_off;
#pragma unroll
        for (int k = 0; k < 8; k++) {
            uint32_t af[2][4], bf[4][4];
            ldsm_x4(aaddr + k * 32,                af[0]);
            ldsm_x4(aaddr + k * 32 + 16 * PITCH_B, af[1]);
#pragma unroll
            for (int ng = 0; ng < 4; ng++)
                ldsm_x4(baddr + k * 32 + ng * 16 * PITCH_B, bf[ng]);
#pragma unroll
            for (int mt = 0; mt < 2; mt++)
#pragma unroll
                for (int nt = 0; nt < 8; nt++)
                    mma16816(acc[mt][nt], af[mt],
                             bf[nt >> 1][(nt & 1) * 2], bf[nt >> 1][(nt & 1) * 2 + 1]);
        }
    }

    // ---- epilogue ----
    const int gq = lane >> 2;          // row within 8-group
    const int tq = lane & 3;           // col pair selector
    if constexpr (MODE == 1) {
#pragma unroll
        for (int mt = 0; mt < 2; mt++) {
            size_t r0 = row0 + m0w + mt * 16 + gq;
            size_t r1 = r0 + 8;
#pragma unroll
            for (int nt = 0; nt < 8; nt++) {
                int c = n0w + nt * 8 + tq * 2;
                float* a = acc[mt][nt];
                *(__half2*)(g_xwh + r0 * 128 + c) = __floats2half2_rn(a[0], a[1]);
                *(__half2*)(g_xwh + r1 * 128 + c) = __floats2half2_rn(a[2], a[3]);
            }
        }
    } else if constexpr (MODE == 2) {
        const float* bias_s = (const float*)(smem + OFF_BIAS);
#pragma unroll
        for (int mt = 0; mt < 2; mt++) {
            size_t r0 = row0 + m0w + mt * 16 + gq;
            size_t r1 = r0 + 8;
#pragma unroll
            for (int nt = 0; nt < 8; nt++) {
                int c = n0w + nt * 8 + tq * 2;
                float b0 = bias_s[c], b1 = bias_s[c + 1];
                float* a = acc[mt][nt];
                *(float2*)(g_h1 + r0 * 128 + c) =
                    make_float2(lrelu(a[0] + b0), lrelu(a[1] + b1));
                *(float2*)(g_h1 + r1 * 128 + c) =
                    make_float2(lrelu(a[2] + b0), lrelu(a[3] + b1));
            }
        }
    } else {
        const float* bias_s = (const float*)(smem + OFF_BIAS);
        const float* w3_s   = (const float*)(smem + OFF_W3);
        float* red = (float*)(smem + OFF_RED);   // [128][2]
#pragma unroll
        for (int mt = 0; mt < 2; mt++) {
            float s0 = 0.0f, s1 = 0.0f;
#pragma unroll
            for (int nt = 0; nt < 8; nt++) {
                int c = n0w + nt * 8 + tq * 2;
                float b0 = bias_s[c], b1 = bias_s[c + 1];
                float w0 = w3_s[c],  w1 = w3_s[c + 1];
                float* a = acc[mt][nt];
                s0 = fmaf(lrelu(a[0] + b0), w0, s0);
                s0 = fmaf(lrelu(a[1] + b1), w1, s0);
                s1 = fmaf(lrelu(a[2] + b0), w0, s1);
                s1 = fmaf(lrelu(a[3] + b1), w1, s1);
            }
            s0 += __shfl_xor_sync(0xffffffffu, s0, 1);
            s0 += __shfl_xor_sync(0xffffffffu, s0, 2);
            s1 += __shfl_xor_sync(0xffffffffu, s1, 1);
            s1 += __shfl_xor_sync(0xffffffffu, s1, 2);
            if (tq == 0) {
                int lr0 = m0w + mt * 16 + gq;
                red[lr0 * 2 + (wid & 1)]       = s0;
                red[(lr0 + 8) * 2 + (wid & 1)] = s1;
            }
        }
        __syncthreads();
        if (tid < 128)
            out[row0 + tid] = red[tid * 2] + red[tid * 2 + 1] + __ldg(b3p);
    }
}

// ---------------------------------------------------------------------------
extern "C" void kernel_launch(void* const* d_in, const int* in_sizes, int n_in,
                              void* d_out, int out_size)
{
    const float* nf  = (const float*)d_in[0];
    const float* act = (const float*)d_in[1];
    const int*   ei  = (const int*)d_in[2];     // JAX x64 disabled -> int32
    const float* Wg  = (const float*)d_in[3];
    const float* bg  = (const float*)d_in[4];
    const float* W1  = (const float*)d_in[5];
    const float* b1  = (const float*)d_in[6];
    const float* W2  = (const float*)d_in[7];
    const float* b2  = (const float*)d_in[8];
    const float* W3  = (const float*)d_in[9];
    const float* b3  = (const float*)d_in[10];
    float* out = (float*)d_out;

    cudaFuncSetAttribute(k_tc<1>, cudaFuncAttributeMaxDynamicSharedMemorySize, SMEM_TOT);
    cudaFuncSetAttribute(k_tc<2>, cudaFuncAttributeMaxDynamicSharedMemorySize, SMEM_TOT);
    cudaFuncSetAttribute(k_tc<3>, cudaFuncAttributeMaxDynamicSharedMemorySize, SMEM_TOT);

    // Edge indexing structure (counting sort by dst)
    k_zero_ideg<<<NBLK, 256>>>();
    k_degree   <<<(Bc * Ec + 255) / 256, 256>>>(ei);
    k_scanA    <<<NBLK, 256>>>();
    k_scanB    <<<1, 1024>>>();
    k_scanC    <<<NBLK, 256>>>();
    k_reorder  <<<(Bc * Ec + 255) / 256, 256>>>(ei);
    k_prep_w   <<<96, 256>>>(Wg, W1, W2);

    // GEMM1: xwh = fp16(concat(nf,act) @ Wg)
    k_tc<1><<<MTOT / 128, 256, SMEM_TOT>>>(nf, act, 0, nullptr, nullptr,
                                           nullptr, nullptr, nullptr);
    // conv = self-loop + gather-aggregate (no atomics, fp16 payload)
    k_aggregate<<<(MTOT * 32 + 255) / 256, 256>>>();
    // GEMM2: h1 = lrelu((relu(conv+bg)+x) @ W1 + b1)
    k_tc<2><<<MTOT / 128, 256, SMEM_TOT>>>(nf, act, 1, b1, bg,
                                           nullptr, nullptr, nullptr);
    // GEMM3 (+ fused head): out = lrelu(h1 @ W2 + b2) @ W3 + b3
    k_tc<3><<<MTOT / 128, 256, SMEM_TOT>>>(nf, act, 2, b2, nullptr,
                                           W3, b3, out);
}

// round 12
// speedup vs baseline: 1.7955x; 1.0457x over previous
#include <cuda_runtime.h>
#include <cuda_bf16.h>
#include <cuda_fp16.h>
#include <cstdint>

// Problem constants
#define Bc  8
#define Nn  20000
#define Ec  320000
#define MTOT (Bc * Nn)          // 160000 rows total
#define NBLK 625                // MTOT / 256
#define LEAKY 0.01f

// Padded bf16 tile: 128 rows x 136 cols (272 B pitch) = 34816 B
#define PITCH_B 272
#define BLOB_B  34816

// Scratch (static device globals — no allocation allowed)
__device__ __half g_xwh[MTOT * 128];   // x @ Wg, fp16 payload for aggregation
__device__ float  g_conv[MTOT * 128];
__device__ float  g_dinv[MTOT];
__device__ int    g_ideg[MTOT];
__device__ int    g_off [MTOT];
__device__ int    g_cur [MTOT];
__device__ int    g_bsum[NBLK];
__device__ int    g_sorted[Bc * Ec];
// Pre-split W blobs in padded B-layout [n][k]: [matrix][hi/lo][BLOB_B/16]
__device__ uint4  g_wblob[3][2][BLOB_B / 16];

__device__ __forceinline__ float lrelu(float v) {
    return fmaxf(v, 0.0f) + LEAKY * fminf(v, 0.0f);
}
__device__ __forceinline__ uint32_t smem_u32(const void* p) {
    uint32_t a;
    asm("{ .reg .u64 t; cvta.to.shared.u64 t, %1; cvt.u32.u64 %0, t; }"
        : "=r"(a) : "l"(p));
    return a;
}
__device__ __forceinline__ void ldsm_x4(uint32_t addr, uint32_t r[4]) {
    asm volatile("ldmatrix.sync.aligned.m8n8.x4.shared.b16 {%0,%1,%2,%3}, [%4];"
                 : "=r"(r[0]), "=r"(r[1]), "=r"(r[2]), "=r"(r[3]) : "r"(addr));
}
__device__ __forceinline__ void mma16816(float* d, const uint32_t a[4],
                                         uint32_t b0, uint32_t b1) {
    asm volatile("mma.sync.aligned.m16n8k16.row.col.f32.bf16.bf16.f32 "
                 "{%0,%1,%2,%3}, {%4,%5,%6,%7}, {%8,%9}, {%0,%1,%2,%3};"
                 : "+f"(d[0]), "+f"(d[1]), "+f"(d[2]), "+f"(d[3])
                 : "r"(a[0]), "r"(a[1]), "r"(a[2]), "r"(a[3]), "r"(b0), "r"(b1));
}
// fp32 pair -> bf16 hi/lo packed words
__device__ __forceinline__ void split2(float v0, float v1, uint32_t& h, uint32_t& l) {
    __nv_bfloat162 hp, lp;
    hp.x = __float2bfloat16(v0); hp.y = __float2bfloat16(v1);
    lp.x = __float2bfloat16(v0 - __bfloat162float(hp.x));
    lp.y = __float2bfloat16(v1 - __bfloat162float(hp.y));
    h = *(uint32_t*)&hp; l = *(uint32_t*)&lp;
}

// ---------------------------------------------------------------------------
// Edge pipeline: degree -> scan -> reorder (counting sort by dst) -> aggregate
// ---------------------------------------------------------------------------
// Fused: zero ideg (all MTOT threads) + W split/layout prep (first 24576)
__global__ void k_init(const float* __restrict__ Wg, const float* __restrict__ W1,
                       const float* __restrict__ W2) {
    int i = blockIdx.x * blockDim.x + threadIdx.x;
    if (i < MTOT) g_ideg[i] = 0;
    if (i < 3 * 8192) {
        int m  = i >> 13;
        int r  = i & 8191;
        int n  = r >> 6;
        int cp = r & 63;
        const float* W = (m == 0) ? Wg : (m == 1) ? W1 : W2;
        float v0 = W[(2 * cp) * 128 + n];     // B[n][2cp] = W[2cp][n]
        float v1 = W[(2 * cp + 1) * 128 + n];
        uint32_t h, l;
        split2(v0, v1, h, l);
        int off = n * PITCH_B + cp * 4;
        *(uint32_t*)((char*)&g_wblob[m][0][0] + off) = h;
        *(uint32_t*)((char*)&g_wblob[m][1][0] + off) = l;
    }
}

__global__ void k_degree(const int* __restrict__ ei) {
    int i = blockIdx.x * blockDim.x + threadIdx.x;
    if (i >= Bc * Ec) return;
    int b = i / Ec;
    int e = i - b * Ec;
    int dst = ei[(size_t)b * 2 * Ec + Ec + e];
    atomicAdd(&g_ideg[b * Nn + dst], 1);
}

__global__ void k_scanA() {
    __shared__ int s[256];
    int i = blockIdx.x * 256 + threadIdx.x;
    int v = g_ideg[i];
    s[threadIdx.x] = v;
    __syncthreads();
#pragma unroll
    for (int d = 1; d < 256; d <<= 1) {
        int t = (threadIdx.x >= d) ? s[threadIdx.x - d] : 0;
        __syncthreads();
        s[threadIdx.x] += t;
        __syncthreads();
    }
    g_off[i] = s[threadIdx.x] - v;
    if (threadIdx.x == 255) g_bsum[blockIdx.x] = s[255];
}

__global__ void k_scanB() {
    __shared__ int s[NBLK];
    int t = threadIdx.x;
    int v = (t < NBLK) ? g_bsum[t] : 0;
    if (t < NBLK) s[t] = v;
    __syncthreads();
    for (int d = 1; d < NBLK; d <<= 1) {
        int x = (t < NBLK && t >= d) ? s[t - d] : 0;
        __syncthreads();
        if (t < NBLK) s[t] += x;
        __syncthreads();
    }
    if (t < NBLK) g_bsum[t] = s[t] - v;
}

__global__ void k_scanC() {
    int i = blockIdx.x * 256 + threadIdx.x;
    int o = g_off[i] + g_bsum[blockIdx.x];
    g_off[i] = o;
    g_cur[i] = o;
    g_dinv[i] = rsqrtf((float)g_ideg[i] + 1.0f);   // +1 self loop
}

__global__ void k_reorder(const int* __restrict__ ei) {
    int i = blockIdx.x * blockDim.x + threadIdx.x;
    if (i >= Bc * Ec) return;
    int b = i / Ec;
    int e = i - b * Ec;
    const int* eb = ei + (size_t)b * 2 * Ec;
    int src = __ldg(&eb[e]);
    int dst = __ldg(&eb[Ec + e]);
    int pos = atomicAdd(&g_cur[b * Nn + dst], 1);
    g_sorted[pos] = b * Nn + src;
}

// One warp per node: conv[i] = xw[i]*dinv[i]^2 + sum_e xw[src]*dinv[src]*dinv[i]
__global__ void k_aggregate() {
    int gw   = (blockIdx.x * blockDim.x + threadIdx.x) >> 5;
    int lane = threadIdx.x & 31;
    if (gw >= MTOT) return;
    const int off = g_off[gw];
    const int deg = g_ideg[gw];
    const float dv = g_dinv[gw];
    const int c = lane * 4;

    const __half2* self = (const __half2*)(g_xwh + (size_t)gw * 128 + c);
    float2 sx = __half22float2(self[0]);
    float2 sy = __half22float2(self[1]);
    float s = dv * dv;
    float ax = sx.x * s, ay = sx.y * s, az = sy.x * s, aw = sy.y * s;

    int e = 0;
    for (; e + 4 <= deg; e += 4) {
        int s0 = g_sorted[off + e + 0];
        int s1 = g_sorted[off + e + 1];
        int s2 = g_sorted[off + e + 2];
        int s3 = g_sorted[off + e + 3];
        float n0 = dv * g_dinv[s0];
        float n1 = dv * g_dinv[s1];
        float n2 = dv * g_dinv[s2];
        float n3 = dv * g_dinv[s3];
        const __half2* p0 = (const __half2*)(g_xwh + (size_t)s0 * 128 + c);
        const __half2* p1 = (const __half2*)(g_xwh + (size_t)s1 * 128 + c);
        const __half2* p2 = (const __half2*)(g_xwh + (size_t)s2 * 128 + c);
        const __half2* p3 = (const __half2*)(g_xwh + (size_t)s3 * 128 + c);
        float2 u0 = __half22float2(p0[0]), w0 = __half22float2(p0[1]);
        float2 u1 = __half22float2(p1[0]), w1 = __half22float2(p1[1]);
        float2 u2 = __half22float2(p2[0]), w2 = __half22float2(p2[1]);
        float2 u3 = __half22float2(p3[0]), w3 = __half22float2(p3[1]);
        ax += u0.x * n0 + u1.x * n1 + u2.x * n2 + u3.x * n3;
        ay += u0.y * n0 + u1.y * n1 + u2.y * n2 + u3.y * n3;
        az += w0.x * n0 + w1.x * n1 + w2.x * n2 + w3.x * n3;
        aw += w0.y * n0 + w1.y * n1 + w2.y * n2 + w3.y * n3;
    }
    for (; e < deg; e++) {
        int s0 = g_sorted[off + e];
        float n0 = dv * g_dinv[s0];
        const __half2* p0 = (const __half2*)(g_xwh + (size_t)s0 * 128 + c);
        float2 u0 = __half22float2(p0[0]), w0 = __half22float2(p0[1]);
        ax += u0.x * n0; ay += u0.y * n0;
        az += w0.x * n0; aw += w0.y * n0;
    }
    *(float4*)(g_conv + (size_t)gw * 128 + c) = make_float4(ax, ay, az, aw);
}

// ---------------------------------------------------------------------------
// Shared GEMM machinery (HMMA bf16x3 split, fp32 accum)
// ---------------------------------------------------------------------------
struct WarpCoords {
    int m0w, n0w;
    uint32_t a_off, b_off;
};
__device__ __forceinline__ WarpCoords warp_coords(int wid, int lane) {
    WarpCoords w;
    w.m0w = (wid >> 1) * 32;
    w.n0w = (wid & 1) * 64;
    w.a_off = (uint32_t)(w.m0w + (lane & 15)) * PITCH_B + ((lane >> 4) ? 16u : 0u);
    w.b_off = (uint32_t)(w.n0w + (lane & 7) + (lane >> 4) * 8) * PITCH_B
            + (((lane >> 3) & 1) ? 16u : 0u);
    return w;
}

// 3 term-passes (AhWh, AhWl, AlWh) x 8 k-chunks into acc[2][8][4]
__device__ __forceinline__ void run_mma(float acc[2][8][4],
                                        uint32_t ah, uint32_t al,
                                        uint32_t wh, uint32_t wl,
                                        const WarpCoords& wc) {
    const uint32_t abase[3] = {ah, ah, al};
    const uint32_t bbase[3] = {wh, wl, wh};
#pragma unroll 1
    for (int pass = 0; pass < 3; pass++) {
        uint32_t aaddr = abase[pass] + wc.a_off;
        uint32_t baddr = bbase[pass] + wc.b_off;
#pragma unroll
        for (int k = 0; k < 8; k++) {
            uint32_t af[2][4], bf[4][4];
            ldsm_x4(aaddr + k * 32,                af[0]);
            ldsm_x4(aaddr + k * 32 + 16 * PITCH_B, af[1]);
#pragma unroll
            for (int ng = 0; ng < 4; ng++)
                ldsm_x4(baddr + k * 32 + ng * 16 * PITCH_B, bf[ng]);
#pragma unroll
            for (int mt = 0; mt < 2; mt++)
#pragma unroll
                for (int nt = 0; nt < 8; nt++)
                    mma16816(acc[mt][nt], af[mt],
                             bf[nt >> 1][(nt & 1) * 2], bf[nt >> 1][(nt & 1) * 2 + 1]);
        }
    }
}

// ---------------------------------------------------------------------------
// GEMM1: xwh = fp16(concat(nf,act) @ Wg).  smem: AH|AL|WH|WL
// ---------------------------------------------------------------------------
#define SMEM1 (4 * BLOB_B)

__global__ __launch_bounds__(256)
void k_tc1(const float* __restrict__ nf, const float* __restrict__ act)
{
    extern __shared__ char smem[];
    const uint32_t sb = smem_u32(smem);
    const int tid  = threadIdx.x;
    const int wid  = tid >> 5;
    const int lane = tid & 31;
    const size_t row0 = (size_t)blockIdx.x * 128;

    {   // W blobs
        const uint4* wh = &g_wblob[0][0][0];
        const uint4* wl = &g_wblob[0][1][0];
        uint4* sh = (uint4*)(smem + 2 * BLOB_B);
        uint4* sl = (uint4*)(smem + 3 * BLOB_B);
        for (int i = tid; i < BLOB_B / 16; i += 256) { sh[i] = wh[i]; sl[i] = wl[i]; }
    }
    {   // A = concat(nf, act)
        int row  = tid >> 1;
        int half = tid & 1;
        size_t rowg = row0 + row;
        const float* srcx = half ? (act + rowg * 64) : (nf + rowg * 64);
        char* ah = smem + row * PITCH_B + half * 128;
        char* al = smem + BLOB_B + row * PITCH_B + half * 128;
#pragma unroll
        for (int q = 0; q < 16; q++) {
            float4 a4 = ((const float4*)srcx)[q];
            uint32_t h, l;
            split2(a4.x, a4.y, h, l);
            *(uint32_t*)(ah + q * 8) = h;  *(uint32_t*)(al + q * 8) = l;
            split2(a4.z, a4.w, h, l);
            *(uint32_t*)(ah + q * 8 + 4) = h;  *(uint32_t*)(al + q * 8 + 4) = l;
        }
    }
    __syncthreads();

    const WarpCoords wc = warp_coords(wid, lane);
    float acc[2][8][4];
#pragma unroll
    for (int mt = 0; mt < 2; mt++)
#pragma unroll
        for (int nt = 0; nt < 8; nt++)
#pragma unroll
            for (int q = 0; q < 4; q++) acc[mt][nt][q] = 0.0f;

    run_mma(acc, sb, sb + BLOB_B, sb + 2 * BLOB_B, sb + 3 * BLOB_B, wc);

    const int gq = lane >> 2;
    const int tq = lane & 3;
#pragma unroll
    for (int mt = 0; mt < 2; mt++) {
        size_t r0 = row0 + wc.m0w + mt * 16 + gq;
        size_t r1 = r0 + 8;
#pragma unroll
        for (int nt = 0; nt < 8; nt++) {
            int c = wc.n0w + nt * 8 + tq * 2;
            float* a = acc[mt][nt];
            *(__half2*)(g_xwh + r0 * 128 + c) = __floats2half2_rn(a[0], a[1]);
            *(__half2*)(g_xwh + r1 * 128 + c) = __floats2half2_rn(a[2], a[3]);
        }
    }
}

// ---------------------------------------------------------------------------
// Fused GEMM2+GEMM3: h1 tile stays in smem (no global round-trip).
//   A = relu(conv+bg)+x ;  h1 = lrelu(A@W1+b1)  -> re-split into A blobs
//   out[row] = lrelu(h1 @ W2 + b2) @ W3 + b3
// smem: AH|AL|W1H|W1L|W2H|W2L | b1 | b2 | W3 | red
// ---------------------------------------------------------------------------
#define OFF23_B1  (6 * BLOB_B)
#define OFF23_B2  (6 * BLOB_B + 512)
#define OFF23_W3  (6 * BLOB_B + 1024)
#define OFF23_RED (6 * BLOB_B + 1536)
#define SMEM23    (6 * BLOB_B + 2560)

__global__ __launch_bounds__(256)
void k_tc23(const float* __restrict__ nf, const float* __restrict__ act,
            const float* __restrict__ bg,
            const float* __restrict__ b1, const float* __restrict__ b2,
            const float* __restrict__ W3, const float* __restrict__ b3p,
            float* __restrict__ out)
{
    extern __shared__ char smem[];
    const uint32_t sb = smem_u32(smem);
    const int tid  = threadIdx.x;
    const int wid  = tid >> 5;
    const int lane = tid & 31;
    const size_t row0 = (size_t)blockIdx.x * 128;

    {   // W1 + W2 blobs
        const uint4* w1h = &g_wblob[1][0][0];
        const uint4* w1l = &g_wblob[1][1][0];
        const uint4* w2h = &g_wblob[2][0][0];
        const uint4* w2l = &g_wblob[2][1][0];
        uint4* s1h = (uint4*)(smem + 2 * BLOB_B);
        uint4* s1l = (uint4*)(smem + 3 * BLOB_B);
        uint4* s2h = (uint4*)(smem + 4 * BLOB_B);
        uint4* s2l = (uint4*)(smem + 5 * BLOB_B);
        for (int i = tid; i < BLOB_B / 16; i += 256) {
            s1h[i] = w1h[i]; s1l[i] = w1l[i];
            s2h[i] = w2h[i]; s2l[i] = w2l[i];
        }
    }
    if (tid < 32)
        ((float4*)(smem + OFF23_B1))[tid] = ((const float4*)b1)[tid];
    else if (tid < 64)
        ((float4*)(smem + OFF23_B2))[tid - 32] = ((const float4*)b2)[tid - 32];
    else if (tid < 96)
        ((float4*)(smem + OFF23_W3))[tid - 64] = ((const float4*)W3)[tid - 64];

    {   // A = relu(conv+bg)+x
        int row  = tid >> 1;
        int half = tid & 1;
        size_t rowg = row0 + row;
        const float* srcx = half ? (act + rowg * 64) : (nf + rowg * 64);
        char* ah = smem + row * PITCH_B + half * 128;
        char* al = smem + BLOB_B + row * PITCH_B + half * 128;
#pragma unroll
        for (int q = 0; q < 16; q++) {
            int c0 = half * 64 + q * 4;
            float4 c4 = *(const float4*)(g_conv + rowg * 128 + c0);
            float4 g4 = __ldg((const float4*)(bg + c0));
            float4 x4 = ((const float4*)srcx)[q];
            float v0 = fmaxf(c4.x + g4.x, 0.0f) + x4.x;
            float v1 = fmaxf(c4.y + g4.y, 0.0f) + x4.y;
            float v2 = fmaxf(c4.z + g4.z, 0.0f) + x4.z;
            float v3 = fmaxf(c4.w + g4.w, 0.0f) + x4.w;
            uint32_t h, l;
            split2(v0, v1, h, l);
            *(uint32_t*)(ah + q * 8) = h;  *(uint32_t*)(al + q * 8) = l;
            split2(v2, v3, h, l);
            *(uint32_t*)(ah + q * 8 + 4) = h;  *(uint32_t*)(al + q * 8 + 4) = l;
        }
    }
    __syncthreads();

    const WarpCoords wc = warp_coords(wid, lane);
    const int gq = lane >> 2;
    const int tq = lane & 3;

    float acc[2][8][4];
#pragma unroll
    for (int mt = 0; mt < 2; mt++)
#pragma unroll
        for (int nt = 0; nt < 8; nt++)
#pragma unroll
            for (int q = 0; q < 4; q++) acc[mt][nt][q] = 0.0f;

    // ---- GEMM2: A @ W1 ----
    run_mma(acc, sb, sb + BLOB_B, sb + 2 * BLOB_B, sb + 3 * BLOB_B, wc);
    __syncthreads();   // everyone done reading A blobs

    // ---- h1 = lrelu(acc + b1) -> re-split into A blobs (smem only) ----
    {
        const float* b1s = (const float*)(smem + OFF23_B1);
        char* ah = smem;
        char* al = smem + BLOB_B;
#pragma unroll
        for (int mt = 0; mt < 2; mt++) {
            int lr0 = wc.m0w + mt * 16 + gq;
            int lr1 = lr0 + 8;
#pragma unroll
            for (int nt = 0; nt < 8; nt++) {
                int c = wc.n0w + nt * 8 + tq * 2;
                float bb0 = b1s[c], bb1 = b1s[c + 1];
                float* a = acc[mt][nt];
                uint32_t h, l;
                split2(lrelu(a[0] + bb0), lrelu(a[1] + bb1), h, l);
                *(uint32_t*)(ah + lr0 * PITCH_B + c * 2) = h;
                *(uint32_t*)(al + lr0 * PITCH_B + c * 2) = l;
                split2(lrelu(a[2] + bb0), lrelu(a[3] + bb1), h, l);
                *(uint32_t*)(ah + lr1 * PITCH_B + c * 2) = h;
                *(uint32_t*)(al + lr1 * PITCH_B + c * 2) = l;
            }
        }
    }
    __syncthreads();

    // ---- GEMM3: h1 @ W2 ----
#pragma unroll
    for (int mt = 0; mt < 2; mt++)
#pragma unroll
        for (int nt = 0; nt < 8; nt++)
#pragma unroll
            for (int q = 0; q < 4; q++) acc[mt][nt][q] = 0.0f;
    run_mma(acc, sb, sb + BLOB_B, sb + 4 * BLOB_B, sb + 5 * BLOB_B, wc);

    // ---- head: out = lrelu(acc + b2) . W3 + b3 ----
    {
        const float* b2s = (const float*)(smem + OFF23_B2);
        const float* w3s = (const float*)(smem + OFF23_W3);
        float* red = (float*)(smem + OFF23_RED);   // [128][2]
#pragma unroll
        for (int mt = 0; mt < 2; mt++) {
            float s0 = 0.0f, s1 = 0.0f;
#pragma unroll
            for (int nt = 0; nt < 8; nt++) {
                int c = wc.n0w + nt * 8 + tq * 2;
                float bb0 = b2s[c], bb1 = b2s[c + 1];
                float w0 = w3s[c],  w1 = w3s[c + 1];
                float* a = acc[mt][nt];
                s0 = fmaf(lrelu(a[0] + bb0), w0, s0);
                s0 = fmaf(lrelu(a[1] + bb1), w1, s0);
                s1 = fmaf(lrelu(a[2] + bb0), w0, s1);
                s1 = fmaf(lrelu(a[3] + bb1), w1, s1);
            }
            s0 += __shfl_xor_sync(0xffffffffu, s0, 1);
            s0 += __shfl_xor_sync(0xffffffffu, s0, 2);
            s1 += __shfl_xor_sync(0xffffffffu, s1, 1);
            s1 += __shfl_xor_sync(0xffffffffu, s1, 2);
            if (tq == 0) {
                int lr0 = wc.m0w + mt * 16 + gq;
                red[lr0 * 2 + (wid & 1)]       = s0;
                red[(lr0 + 8) * 2 + (wid & 1)] = s1;
            }
        }
        __syncthreads();
        if (tid < 128)
            out[row0 + tid] = red[tid * 2] + red[tid * 2 + 1] + __ldg(b3p);
    }
}

// ---------------------------------------------------------------------------
extern "C" void kernel_launch(void* const* d_in, const int* in_sizes, int n_in,
                              void* d_out, int out_size)
{
    const float* nf  = (const float*)d_in[0];
    const float* act = (const float*)d_in[1];
    const int*   ei  = (const int*)d_in[2];     // JAX x64 disabled -> int32
    const float* Wg  = (const float*)d_in[3];
    const float* bg  = (const float*)d_in[4];
    const float* W1  = (const float*)d_in[5];
    const float* b1  = (const float*)d_in[6];
    const float* W2  = (const float*)d_in[7];
    const float* b2  = (const float*)d_in[8];
    const float* W3  = (const float*)d_in[9];
    const float* b3  = (const float*)d_in[10];
    float* out = (float*)d_out;

    cudaFuncSetAttribute(k_tc1,  cudaFuncAttributeMaxDynamicSharedMemorySize, SMEM1);
    cudaFuncSetAttribute(k_tc23, cudaFuncAttributeMaxDynamicSharedMemorySize, SMEM23);

    // Edge indexing structure (counting sort by dst) + weight prep
    k_init    <<<NBLK, 256>>>(Wg, W1, W2);
    k_degree  <<<(Bc * Ec + 255) / 256, 256>>>(ei);
    k_scanA   <<<NBLK, 256>>>();
    k_scanB   <<<1, 1024>>>();
    k_scanC   <<<NBLK, 256>>>();
    k_reorder <<<(Bc * Ec + 255) / 256, 256>>>(ei);

    // GEMM1: xwh = fp16(concat(nf,act) @ Wg)
    k_tc1<<<MTOT / 128, 256, SMEM1>>>(nf, act);
    // conv = self-loop + gather-aggregate (no atomics, fp16 payload)
    k_aggregate<<<(MTOT * 32 + 255) / 256, 256>>>();
    // Fused GEMM2+GEMM3 (+head): no h1 global round-trip
    k_tc23<<<MTOT / 128, 256, SMEM23>>>(nf, act, bg, b1, b2, W3, b3, out);
}

// round 14
// speedup vs baseline: 1.9363x; 1.0784x over previous
#include <cuda_runtime.h>
#include <cuda_bf16.h>
#include <cuda_fp16.h>
#include <cstdint>

// Problem constants
#define Bc  8
#define Nn  20000
#define Ec  320000
#define MTOT (Bc * Nn)          // 160000 rows total
#define NBLK 625                // MTOT / 256
#define NTILE (MTOT / 128)      // 1250 GEMM tiles
#define NSM  148
#define LEAKY 0.01f

// Padded bf16 tile: 128 rows x 136 cols (272 B pitch) = 34816 B
#define PITCH_B 272
#define BLOB_B  34816

// Scratch (static device globals — no allocation allowed)
__device__ __half g_xwh[MTOT * 128];   // fp16(xw * dinv_row)  [pre-scaled payload]
__device__ float  g_conv[MTOT * 128];
__device__ float  g_dinv[MTOT];
__device__ int    g_ideg[MTOT];
__device__ int    g_off [MTOT];
__device__ int    g_cur [MTOT];
__device__ int    g_bsum[NBLK];
__device__ int    g_sorted[Bc * Ec];
// Pre-split W blobs in padded B-layout [n][k]: [matrix][hi/lo][BLOB_B/16]
__device__ uint4  g_wblob[3][2][BLOB_B / 16];

__device__ __forceinline__ float lrelu(float v) {
    return fmaxf(v, 0.0f) + LEAKY * fminf(v, 0.0f);
}
__device__ __forceinline__ uint32_t smem_u32(const void* p) {
    uint32_t a;
    asm("{ .reg .u64 t; cvta.to.shared.u64 t, %1; cvt.u32.u64 %0, t; }"
        : "=r"(a) : "l"(p));
    return a;
}
__device__ __forceinline__ void ldsm_x4(uint32_t addr, uint32_t r[4]) {
    asm volatile("ldmatrix.sync.aligned.m8n8.x4.shared.b16 {%0,%1,%2,%3}, [%4];"
                 : "=r"(r[0]), "=r"(r[1]), "=r"(r[2]), "=r"(r[3]) : "r"(addr));
}
__device__ __forceinline__ void mma16816(float* d, const uint32_t a[4],
                                         uint32_t b0, uint32_t b1) {
    asm volatile("mma.sync.aligned.m16n8k16.row.col.f32.bf16.bf16.f32 "
                 "{%0,%1,%2,%3}, {%4,%5,%6,%7}, {%8,%9}, {%0,%1,%2,%3};"
                 : "+f"(d[0]), "+f"(d[1]), "+f"(d[2]), "+f"(d[3])
                 : "r"(a[0]), "r"(a[1]), "r"(a[2]), "r"(a[3]), "r"(b0), "r"(b1));
}
__device__ __forceinline__ void split2(float v0, float v1, uint32_t& h, uint32_t& l) {
    __nv_bfloat162 hp, lp;
    hp.x = __float2bfloat16(v0); hp.y = __float2bfloat16(v1);
    lp.x = __float2bfloat16(v0 - __bfloat162float(hp.x));
    lp.y = __float2bfloat16(v1 - __bfloat162float(hp.y));
    h = *(uint32_t*)&hp; l = *(uint32_t*)&lp;
}
__device__ __forceinline__ float4 h4_to_f4(uint2 v) {
    float2 a = __half22float2(*(__half2*)&v.x);
    float2 b = __half22float2(*(__half2*)&v.y);
    return make_float4(a.x, a.y, b.x, b.y);
}

// ---------------------------------------------------------------------------
// Edge pipeline: degree -> scan -> reorder (counting sort by dst) -> aggregate
// ---------------------------------------------------------------------------
__global__ void k_init(const float* __restrict__ Wg, const float* __restrict__ W1,
                       const float* __restrict__ W2) {
    int i = blockIdx.x * blockDim.x + threadIdx.x;
    if (i < MTOT) g_ideg[i] = 0;
    if (i < 3 * 8192) {
        int m  = i >> 13;
        int r  = i & 8191;
        int n  = r >> 6;
        int cp = r & 63;
        const float* W = (m == 0) ? Wg : (m == 1) ? W1 : W2;
        float v0 = W[(2 * cp) * 128 + n];     // B[n][2cp] = W[2cp][n]
        float v1 = W[(2 * cp + 1) * 128 + n];
        uint32_t h, l;
        split2(v0, v1, h, l);
        int off = n * PITCH_B + cp * 4;
        *(uint32_t*)((char*)&g_wblob[m][0][0] + off) = h;
        *(uint32_t*)((char*)&g_wblob[m][1][0] + off) = l;
    }
}

__global__ void k_degree(const int* __restrict__ ei) {
    int i = blockIdx.x * blockDim.x + threadIdx.x;
    if (i >= Bc * Ec) return;
    int b = i / Ec;
    int e = i - b * Ec;
    int dst = ei[(size_t)b * 2 * Ec + Ec + e];
    atomicAdd(&g_ideg[b * Nn + dst], 1);
}

__global__ void k_scanA() {
    __shared__ int s[256];
    int i = blockIdx.x * 256 + threadIdx.x;
    int v = g_ideg[i];
    s[threadIdx.x] = v;
    __syncthreads();
#pragma unroll
    for (int d = 1; d < 256; d <<= 1) {
        int t = (threadIdx.x >= d) ? s[threadIdx.x - d] : 0;
        __syncthreads();
        s[threadIdx.x] += t;
        __syncthreads();
    }
    g_off[i] = s[threadIdx.x] - v;
    if (threadIdx.x == 255) g_bsum[blockIdx.x] = s[255];
}

__global__ void k_scanB() {
    __shared__ int s[NBLK];
    int t = threadIdx.x;
    int v = (t < NBLK) ? g_bsum[t] : 0;
    if (t < NBLK) s[t] = v;
    __syncthreads();
    for (int d = 1; d < NBLK; d <<= 1) {
        int x = (t < NBLK && t >= d) ? s[t - d] : 0;
        __syncthreads();
        if (t < NBLK) s[t] += x;
        __syncthreads();
    }
    if (t < NBLK) g_bsum[t] = s[t] - v;
}

__global__ void k_scanC() {
    int i = blockIdx.x * 256 + threadIdx.x;
    int o = g_off[i] + g_bsum[blockIdx.x];
    g_off[i] = o;
    g_cur[i] = o;
    g_dinv[i] = rsqrtf((float)g_ideg[i] + 1.0f);   // +1 self loop
}

__global__ void k_reorder(const int* __restrict__ ei) {
    int i = blockIdx.x * blockDim.x + threadIdx.x;
    if (i >= Bc * Ec) return;
    int b = i / Ec;
    int e = i - b * Ec;
    const int* eb = ei + (size_t)b * 2 * Ec;
    int src = __ldg(&eb[e]);
    int dst = __ldg(&eb[Ec + e]);
    int pos = atomicAdd(&g_cur[b * Nn + dst], 1);
    g_sorted[pos] = b * Nn + src;
}

// One warp per node: conv[i] = dinv[i] * ( xwh'[i] + sum_e xwh'[src] )
// where xwh' = xw*dinv. Self term: dinv*xwh'[i] = xw*dinv^2 (correct).
__global__ void k_aggregate() {
    int gw   = (blockIdx.x * blockDim.x + threadIdx.x) >> 5;
    int lane = threadIdx.x & 31;
    if (gw >= MTOT) return;
    const int off = g_off[gw];
    const int deg = g_ideg[gw];
    const float dv = g_dinv[gw];

    const uint2* base = (const uint2*)g_xwh;   // 8B = 4 halves per lane
    uint2 sv = base[(size_t)gw * 32 + lane];
    float4 sf = h4_to_f4(sv);
    float ax = sf.x, ay = sf.y, az = sf.z, aw = sf.w;   // raw self payload

    int e = 0;
    for (; e + 4 <= deg; e += 4) {
        int s0 = g_sorted[off + e + 0];
        int s1 = g_sorted[off + e + 1];
        int s2 = g_sorted[off + e + 2];
        int s3 = g_sorted[off + e + 3];
        uint2 v0 = base[(size_t)s0 * 32 + lane];
        uint2 v1 = base[(size_t)s1 * 32 + lane];
        uint2 v2 = base[(size_t)s2 * 32 + lane];
        uint2 v3 = base[(size_t)s3 * 32 + lane];
        float4 f0 = h4_to_f4(v0), f1 = h4_to_f4(v1);
        float4 f2 = h4_to_f4(v2), f3 = h4_to_f4(v3);
        ax += f0.x + f1.x + f2.x + f3.x;
        ay += f0.y + f1.y + f2.y + f3.y;
        az += f0.z + f1.z + f2.z + f3.z;
        aw += f0.w + f1.w + f2.w + f3.w;
    }
    for (; e < deg; e++) {
        int s0 = g_sorted[off + e];
        float4 f0 = h4_to_f4(base[(size_t)s0 * 32 + lane]);
        ax += f0.x; ay += f0.y; az += f0.z; aw += f0.w;
    }
    *(float4*)(g_conv + (size_t)gw * 128 + lane * 4) =
        make_float4(ax * dv, ay * dv, az * dv, aw * dv);
}

// ---------------------------------------------------------------------------
// Shared GEMM machinery (HMMA bf16x3 split, fp32 accum)
// ---------------------------------------------------------------------------
struct WarpCoords {
    int m0w, n0w;
    uint32_t a_off, b_off;
};
__device__ __forceinline__ WarpCoords warp_coords(int wid, int lane) {
    WarpCoords w;
    w.m0w = (wid >> 1) * 32;
    w.n0w = (wid & 1) * 64;
    w.a_off = (uint32_t)(w.m0w + (lane & 15)) * PITCH_B + ((lane >> 4) ? 16u : 0u);
    w.b_off = (uint32_t)(w.n0w + (lane & 7) + (lane >> 4) * 8) * PITCH_B
            + (((lane >> 3) & 1) ? 16u : 0u);
    return w;
}

__device__ __forceinline__ void run_mma(float acc[2][8][4],
                                        uint32_t ah, uint32_t al,
                                        uint32_t wh, uint32_t wl,
                                        const WarpCoords& wc) {
    const uint32_t abase[3] = {ah, ah, al};
    const uint32_t bbase[3] = {wh, wl, wh};
#pragma unroll 1
    for (int pass = 0; pass < 3; pass++) {
        uint32_t aaddr = abase[pass] + wc.a_off;
        uint32_t baddr = bbase[pass] + wc.b_off;
#pragma unroll
        for (int k = 0; k < 8; k++) {
            uint32_t af[2][4], bf[4][4];
            ldsm_x4(aaddr + k * 32,                af[0]);
            ldsm_x4(aaddr + k * 32 + 16 * PITCH_B, af[1]);
#pragma unroll
            for (int ng = 0; ng < 4; ng++)
                ldsm_x4(baddr + k * 32 + ng * 16 * PITCH_B, bf[ng]);
#pragma unroll
            for (int mt = 0; mt < 2; mt++)
#pragma unroll
                for (int nt = 0; nt < 8; nt++)
                    mma16816(acc[mt][nt], af[mt],
                             bf[nt >> 1][(nt & 1) * 2], bf[nt >> 1][(nt & 1) * 2 + 1]);
        }
    }
}

// ---------------------------------------------------------------------------
// GEMM1 (persistent): xwh = fp16((concat(nf,act) @ Wg) * dinv_row)
// smem: AH|AL|WH|WL
// ---------------------------------------------------------------------------
#define SMEM1 (4 * BLOB_B)

__global__ __launch_bounds__(256)
void k_tc1(const float* __restrict__ nf, const float* __restrict__ act)
{
    extern __shared__ char smem[];
    const uint32_t sb = smem_u32(smem);
    const int tid  = threadIdx.x;
    const int wid  = tid >> 5;
    const int lane = tid & 31;

    {   // W blobs (once per SM)
        const uint4* wh = &g_wblob[0][0][0];
        const uint4* wl = &g_wblob[0][1][0];
        uint4* sh = (uint4*)(smem + 2 * BLOB_B);
        uint4* sl = (uint4*)(smem + 3 * BLOB_B);
        for (int i = tid; i < BLOB_B / 16; i += 256) { sh[i] = wh[i]; sl[i] = wl[i]; }
    }
    const WarpCoords wc = warp_coords(wid, lane);
    const int gq = lane >> 2;
    const int tq = lane & 3;

    for (int tile = blockIdx.x; tile < NTILE; tile += gridDim.x) {
        const size_t row0 = (size_t)tile * 128;
        {   // A = concat(nf, act)
            int row  = tid >> 1;
            int half = tid & 1;
            size_t rowg = row0 + row;
            const float* srcx = half ? (act + rowg * 64) : (nf + rowg * 64);
            char* ah = smem + row * PITCH_B + half * 128;
            char* al = smem + BLOB_B + row * PITCH_B + half * 128;
#pragma unroll
            for (int q = 0; q < 16; q++) {
                float4 a4 = ((const float4*)srcx)[q];
                uint32_t h, l;
                split2(a4.x, a4.y, h, l);
                *(uint32_t*)(ah + q * 8) = h;  *(uint32_t*)(al + q * 8) = l;
                split2(a4.z, a4.w, h, l);
                *(uint32_t*)(ah + q * 8 + 4) = h;  *(uint32_t*)(al + q * 8 + 4) = l;
            }
        }
        __syncthreads();

        float acc[2][8][4];
#pragma unroll
        for (int mt = 0; mt < 2; mt++)
#pragma unroll
            for (int nt = 0; nt < 8; nt++)
#pragma unroll
                for (int q = 0; q < 4; q++) acc[mt][nt][q] = 0.0f;

        run_mma(acc, sb, sb + BLOB_B, sb + 2 * BLOB_B, sb + 3 * BLOB_B, wc);

#pragma unroll
        for (int mt = 0; mt < 2; mt++) {
            size_t r0 = row0 + wc.m0w + mt * 16 + gq;
            size_t r1 = r0 + 8;
            float d0 = g_dinv[r0], d1 = g_dinv[r1];
#pragma unroll
            for (int nt = 0; nt < 8; nt++) {
                int c = wc.n0w + nt * 8 + tq * 2;
                float* a = acc[mt][nt];
                *(__half2*)(g_xwh + r0 * 128 + c) =
                    __floats2half2_rn(a[0] * d0, a[1] * d0);
                *(__half2*)(g_xwh + r1 * 128 + c) =
                    __floats2half2_rn(a[2] * d1, a[3] * d1);
            }
        }
        __syncthreads();   // all mma reads of A done before next tile's A build
    }
}

// ---------------------------------------------------------------------------
// Fused GEMM2+GEMM3 (persistent): h1 tile stays in smem.
// smem: AH|AL|W1H|W1L|W2H|W2L | b1 | b2 | W3 | red
// ---------------------------------------------------------------------------
#define OFF23_B1  (6 * BLOB_B)
#define OFF23_B2  (6 * BLOB_B + 512)
#define OFF23_W3  (6 * BLOB_B + 1024)
#define OFF23_RED (6 * BLOB_B + 1536)
#define SMEM23    (6 * BLOB_B + 2560)

__global__ __launch_bounds__(256)
void k_tc23(const float* __restrict__ nf, const float* __restrict__ act,
            const float* __restrict__ bg,
            const float* __restrict__ b1, const float* __restrict__ b2,
            const float* __restrict__ W3, const float* __restrict__ b3p,
            float* __restrict__ out)
{
    extern __shared__ char smem[];
    const uint32_t sb = smem_u32(smem);
    const int tid  = threadIdx.x;
    const int wid  = tid >> 5;
    const int lane = tid & 31;

    {   // W1 + W2 blobs + biases (once per SM)
        const uint4* w1h = &g_wblob[1][0][0];
        const uint4* w1l = &g_wblob[1][1][0];
        const uint4* w2h = &g_wblob[2][0][0];
        const uint4* w2l = &g_wblob[2][1][0];
        uint4* s1h = (uint4*)(smem + 2 * BLOB_B);
        uint4* s1l = (uint4*)(smem + 3 * BLOB_B);
        uint4* s2h = (uint4*)(smem + 4 * BLOB_B);
        uint4* s2l = (uint4*)(smem + 5 * BLOB_B);
        for (int i = tid; i < BLOB_B / 16; i += 256) {
            s1h[i] = w1h[i]; s1l[i] = w1l[i];
            s2h[i] = w2h[i]; s2l[i] = w2l[i];
        }
    }
    if (tid < 32)
        ((float4*)(smem + OFF23_B1))[tid] = ((const float4*)b1)[tid];
    else if (tid < 64)
        ((float4*)(smem + OFF23_B2))[tid - 32] = ((const float4*)b2)[tid - 32];
    else if (tid < 96)
        ((float4*)(smem + OFF23_W3))[tid - 64] = ((const float4*)W3)[tid - 64];

    const WarpCoords wc = warp_coords(wid, lane);
    const int gq = lane >> 2;
    const int tq = lane & 3;
    const float b3v = __ldg(b3p);

    for (int tile = blockIdx.x; tile < NTILE; tile += gridDim.x) {
        const size_t row0 = (size_t)tile * 128;
        {   // A = relu(conv+bg)+x
            int row  = tid >> 1;
            int half = tid & 1;
            size_t rowg = row0 + row;
            const float* srcx = half ? (act + rowg * 64) : (nf + rowg * 64);
            char* ah = smem + row * PITCH_B + half * 128;
            char* al = smem + BLOB_B + row * PITCH_B + half * 128;
#pragma unroll
            for (int q = 0; q < 16; q++) {
                int c0 = half * 64 + q * 4;
                float4 c4 = *(const float4*)(g_conv + rowg * 128 + c0);
                float4 g4 = __ldg((const float4*)(bg + c0));
                float4 x4 = ((const float4*)srcx)[q];
                float v0 = fmaxf(c4.x + g4.x, 0.0f) + x4.x;
                float v1 = fmaxf(c4.y + g4.y, 0.0f) + x4.y;
                float v2 = fmaxf(c4.z + g4.z, 0.0f) + x4.z;
                float v3 = fmaxf(c4.w + g4.w, 0.0f) + x4.w;
                uint32_t h, l;
                split2(v0, v1, h, l);
                *(uint32_t*)(ah + q * 8) = h;  *(uint32_t*)(al + q * 8) = l;
                split2(v2, v3, h, l);
                *(uint32_t*)(ah + q * 8 + 4) = h;  *(uint32_t*)(al + q * 8 + 4) = l;
            }
        }
        __syncthreads();

        float acc[2][8][4];
#pragma unroll
        for (int mt = 0; mt < 2; mt++)
#pragma unroll
            for (int nt = 0; nt < 8; nt++)
#pragma unroll
                for (int q = 0; q < 4; q++) acc[mt][nt][q] = 0.0f;

        // ---- GEMM2: A @ W1 ----
        run_mma(acc, sb, sb + BLOB_B, sb + 2 * BLOB_B, sb + 3 * BLOB_B, wc);
        __syncthreads();

        // ---- h1 = lrelu(acc + b1) -> re-split into A blobs ----
        {
            const float* b1s = (const float*)(smem + OFF23_B1);
            char* ah = smem;
            char* al = smem + BLOB_B;
#pragma unroll
            for (int mt = 0; mt < 2; mt++) {
                int lr0 = wc.m0w + mt * 16 + gq;
                int lr1 = lr0 + 8;
#pragma unroll
                for (int nt = 0; nt < 8; nt++) {
                    int c = wc.n0w + nt * 8 + tq * 2;
                    float bb0 = b1s[c], bb1 = b1s[c + 1];
                    float* a = acc[mt][nt];
                    uint32_t h, l;
                    split2(lrelu(a[0] + bb0), lrelu(a[1] + bb1), h, l);
                    *(uint32_t*)(ah + lr0 * PITCH_B + c * 2) = h;
                    *(uint32_t*)(al + lr0 * PITCH_B + c * 2) = l;
                    split2(lrelu(a[2] + bb0), lrelu(a[3] + bb1), h, l);
                    *(uint32_t*)(ah + lr1 * PITCH_B + c * 2) = h;
                    *(uint32_t*)(al + lr1 * PITCH_B + c * 2) = l;
                }
            }
        }
        __syncthreads();

        // ---- GEMM3: h1 @ W2 ----
#pragma unroll
        for (int mt = 0; mt < 2; mt++)
#pragma unroll
            for (int nt = 0; nt < 8; nt++)
#pragma unroll
                for (int q = 0; q < 4; q++) acc[mt][nt][q] = 0.0f;
        run_mma(acc, sb, sb + BLOB_B, sb + 4 * BLOB_B, sb + 5 * BLOB_B, wc);

        // ---- head: out = lrelu(acc + b2) . W3 + b3 ----
        {
            const float* b2s = (const float*)(smem + OFF23_B2);
            const float* w3s = (const float*)(smem + OFF23_W3);
            float* red = (float*)(smem + OFF23_RED);   // [128][2]
#pragma unroll
            for (int mt = 0; mt < 2; mt++) {
                float s0 = 0.0f, s1 = 0.0f;
#pragma unroll
                for (int nt = 0; nt < 8; nt++) {
                    int c = wc.n0w + nt * 8 + tq * 2;
                    float bb0 = b2s[c], bb1 = b2s[c + 1];
                    float w0 = w3s[c],  w1 = w3s[c + 1];
                    float* a = acc[mt][nt];
                    s0 = fmaf(lrelu(a[0] + bb0), w0, s0);
                    s0 = fmaf(lrelu(a[1] + bb1), w1, s0);
                    s1 = fmaf(lrelu(a[2] + bb0), w0, s1);
                    s1 = fmaf(lrelu(a[3] + bb1), w1, s1);
                }
                s0 += __shfl_xor_sync(0xffffffffu, s0, 1);
                s0 += __shfl_xor_sync(0xffffffffu, s0, 2);
                s1 += __shfl_xor_sync(0xffffffffu, s1, 1);
                s1 += __shfl_xor_sync(0xffffffffu, s1, 2);
                if (tq == 0) {
                    int lr0 = wc.m0w + mt * 16 + gq;
                    red[lr0 * 2 + (wid & 1)]       = s0;
                    red[(lr0 + 8) * 2 + (wid & 1)] = s1;
                }
            }
            __syncthreads();   // also guards next tile's A-blob overwrite
            if (tid < 128)
                out[row0 + tid] = red[tid * 2] + red[tid * 2 + 1] + b3v;
        }
    }
}

// ---------------------------------------------------------------------------
extern "C" void kernel_launch(void* const* d_in, const int* in_sizes, int n_in,
                              void* d_out, int out_size)
{
    const float* nf  = (const float*)d_in[0];
    const float* act = (const float*)d_in[1];
    const int*   ei  = (const int*)d_in[2];     // JAX x64 disabled -> int32
    const float* Wg  = (const float*)d_in[3];
    const float* bg  = (const float*)d_in[4];
    const float* W1  = (const float*)d_in[5];
    const float* b1  = (const float*)d_in[6];
    const float* W2  = (const float*)d_in[7];
    const float* b2  = (const float*)d_in[8];
    const float* W3  = (const float*)d_in[9];
    const float* b3  = (const float*)d_in[10];
    float* out = (float*)d_out;

    cudaFuncSetAttribute(k_tc1,  cudaFuncAttributeMaxDynamicSharedMemorySize, SMEM1);
    cudaFuncSetAttribute(k_tc23, cudaFuncAttributeMaxDynamicSharedMemorySize, SMEM23);

    // Edge indexing structure (counting sort by dst) + weight prep
    k_init    <<<NBLK, 256>>>(Wg, W1, W2);
    k_degree  <<<(Bc * Ec + 255) / 256, 256>>>(ei);
    k_scanA   <<<NBLK, 256>>>();
    k_scanB   <<<1, 1024>>>();
    k_scanC   <<<NBLK, 256>>>();
    k_reorder <<<(Bc * Ec + 255) / 256, 256>>>(ei);

    // GEMM1 (persistent): xwh = fp16((concat(nf,act) @ Wg) * dinv)
    k_tc1<<<NSM, 256, SMEM1>>>(nf, act);
    // conv = dinv * (self + gather-sum)  [2 LDG/warp/edge]
    k_aggregate<<<(MTOT * 32 + 255) / 256, 256>>>();
    // Fused GEMM2+GEMM3 (persistent, +head)
    k_tc23<<<NSM, 256, SMEM23>>>(nf, act, bg, b1, b2, W3, b3, out);
}